// round 1
// baseline (speedup 1.0000x reference)
#include <cuda_runtime.h>
#include <math.h>

// Problem constants
#define B_    4
#define N_    1024
#define C_    1024
#define H_    16
#define DH    64
#define DHID  4096
#define R_    (B_*N_)   // 4096 token rows

// ---------------- scratch (device globals: allocation-guard safe) ----------
__device__ float g_h  [R_*C_];          // 16 MB  (LN outputs, reused)
__device__ float g_qkv[R_*3*C_];        // 48 MB
__device__ float g_o  [R_*C_];          // 16 MB  (attention output, [B,N,C])
__device__ float g_x1 [R_*C_];          // 16 MB  (residual after attention)
__device__ float g_u  [R_*DHID];        // 64 MB  (MLP hidden)

// ---------------- LayerNorm: one block per row -----------------------------
__global__ void ln_kernel(const float* __restrict__ x,
                          const float* __restrict__ g,
                          const float* __restrict__ bb,
                          float* __restrict__ y, int C)
{
    int row = blockIdx.x;
    int tid = threadIdx.x;
    const float* xr = x + (size_t)row * C;
    float*       yr = y + (size_t)row * C;

    float s = 0.f, sq = 0.f;
    for (int i = tid * 4; i < C; i += 256 * 4) {
        float4 v = *(const float4*)(xr + i);
        s  += v.x + v.y + v.z + v.w;
        sq += v.x*v.x + v.y*v.y + v.z*v.z + v.w*v.w;
    }
    for (int o = 16; o > 0; o >>= 1) {
        s  += __shfl_xor_sync(0xffffffffu, s,  o);
        sq += __shfl_xor_sync(0xffffffffu, sq, o);
    }
    __shared__ float rs[8], rq[8], stats[2];
    int w = tid >> 5, ln = tid & 31;
    if (ln == 0) { rs[w] = s; rq[w] = sq; }
    __syncthreads();
    if (tid == 0) {
        float ts = 0.f, tq = 0.f;
        #pragma unroll
        for (int i = 0; i < 8; i++) { ts += rs[i]; tq += rq[i]; }
        float mu  = ts / (float)C;
        float var = tq / (float)C - mu * mu;
        stats[0] = mu;
        stats[1] = rsqrtf(var + 1e-5f);
    }
    __syncthreads();
    float mu = stats[0], r = stats[1];
    for (int i = tid * 4; i < C; i += 256 * 4) {
        float4 v  = *(const float4*)(xr + i);
        float4 gg = *(const float4*)(g  + i);
        float4 be = *(const float4*)(bb + i);
        float4 o4;
        o4.x = (v.x - mu) * r * gg.x + be.x;
        o4.y = (v.y - mu) * r * gg.y + be.y;
        o4.z = (v.z - mu) * r * gg.z + be.z;
        o4.w = (v.w - mu) * r * gg.w + be.w;
        *(float4*)(yr + i) = o4;
    }
}

// ---------------- SGEMM (NT): C[M,N] = A[M,K] @ B[N,K]^T + epilogue --------
// EPI: 0 = plain, 1 = +bias then erf-GELU, 2 = +bias +residual
template<int EPI>
__global__ void __launch_bounds__(256)
sgemm_nt(const float* __restrict__ A, const float* __restrict__ Bm,
         float* __restrict__ C, const float* __restrict__ bias,
         const float* __restrict__ res, int M, int N, int K)
{
    constexpr int BM = 128, BN = 128, BK = 8;
    __shared__ float As[BK][BM];
    __shared__ float Bs[BK][BN];

    int tid  = threadIdx.x;
    int row0 = blockIdx.y * BM;
    int col0 = blockIdx.x * BN;

    int lr = tid >> 1;          // 0..127
    int lc = (tid & 1) * 4;     // 0 or 4
    const float* Ap = A  + (size_t)(row0 + lr) * K + lc;
    const float* Bp = Bm + (size_t)(col0 + lr) * K + lc;

    int ty = tid >> 4, tx = tid & 15;
    float acc[8][8] = {};

    for (int k0 = 0; k0 < K; k0 += BK) {
        float4 a4 = *(const float4*)(Ap + k0);
        float4 b4 = *(const float4*)(Bp + k0);
        __syncthreads();
        As[lc+0][lr] = a4.x; As[lc+1][lr] = a4.y;
        As[lc+2][lr] = a4.z; As[lc+3][lr] = a4.w;
        Bs[lc+0][lr] = b4.x; Bs[lc+1][lr] = b4.y;
        Bs[lc+2][lr] = b4.z; Bs[lc+3][lr] = b4.w;
        __syncthreads();
        #pragma unroll
        for (int kk = 0; kk < BK; kk++) {
            float a[8], b[8];
            *(float4*)(a)     = *(const float4*)&As[kk][ty*8];
            *(float4*)(a + 4) = *(const float4*)&As[kk][ty*8 + 4];
            *(float4*)(b)     = *(const float4*)&Bs[kk][tx*8];
            *(float4*)(b + 4) = *(const float4*)&Bs[kk][tx*8 + 4];
            #pragma unroll
            for (int i = 0; i < 8; i++)
                #pragma unroll
                for (int j = 0; j < 8; j++)
                    acc[i][j] += a[i] * b[j];
        }
    }

    #pragma unroll
    for (int i = 0; i < 8; i++) {
        int r = row0 + ty*8 + i;
        #pragma unroll
        for (int j = 0; j < 8; j++) {
            int c = col0 + tx*8 + j;
            float v = acc[i][j];
            if (EPI >= 1) v += bias[c];
            if (EPI == 1) v = 0.5f * v * (1.f + erff(v * 0.70710678118654752f));
            if (EPI == 2) v += res[(size_t)r * N + c];
            C[(size_t)r * N + c] = v;
        }
    }
}

// ---------------- Flash attention (fp32, online softmax) -------------------
// grid: (N/128, H, B); block: 128 threads; thread t handles query row t.
// qkv layout per token row (stride 3C): [q(0:1024) | k(1024:2048) | v(2048:3072)]
// within each: head*64 + d.  Output written directly in [B,N,C] layout.
__global__ void __launch_bounds__(128)
attn_kernel(const float* __restrict__ qkv, float* __restrict__ o)
{
    constexpr int TQ = 128, TK = 32, D = 64;
    __shared__ float Ks[TK][D];        // 8 KB
    __shared__ float Vs[TK][D];        // 8 KB
    __shared__ float Ps[TQ][TK + 1];   // padded: conflict-free per-thread rows

    int tid = threadIdx.x;
    int b = blockIdx.z, h = blockIdx.y;
    int q = blockIdx.x * TQ + tid;
    const int RS = 3 * C_;

    const float* qp = qkv + ((size_t)(b * N_ + q)) * RS + h * DH;
    float qv[D];
    #pragma unroll
    for (int dd = 0; dd < 16; dd++)
        *(float4*)(qv + 4*dd) = *(const float4*)(qp + 4*dd);

    float acc[D] = {};
    float m = -1e30f, l = 0.f;
    const float scale = 0.125f;   // 64^-0.5

    for (int t = 0; t < N_ / TK; t++) {
        __syncthreads();
        // cooperative K/V tile load: TK keys x 16 float4 each
        for (int i = tid; i < TK * 16; i += TQ) {
            int key = i >> 4, dd = i & 15;
            const float* base = qkv + ((size_t)(b * N_ + t * TK + key)) * RS + h * DH;
            *(float4*)&Ks[key][dd*4] = *(const float4*)(base + C_     + dd*4);
            *(float4*)&Vs[key][dd*4] = *(const float4*)(base + 2*C_   + dd*4);
        }
        __syncthreads();

        // scores (broadcast LDS reads)
        float tmax = -1e30f;
        for (int j = 0; j < TK; j++) {
            float s = 0.f;
            const float4* kr = (const float4*)Ks[j];
            #pragma unroll
            for (int dd = 0; dd < 16; dd++) {
                float4 kv = kr[dd];
                s += qv[4*dd+0]*kv.x + qv[4*dd+1]*kv.y
                   + qv[4*dd+2]*kv.z + qv[4*dd+3]*kv.w;
            }
            s *= scale;
            Ps[tid][j] = s;
            tmax = fmaxf(tmax, s);
        }

        // online softmax update
        float mnew = fmaxf(m, tmax);
        float corr = __expf(m - mnew);
        l *= corr;
        #pragma unroll
        for (int d = 0; d < D; d++) acc[d] *= corr;
        float ls = 0.f;
        for (int j = 0; j < TK; j++) {
            float p = __expf(Ps[tid][j] - mnew);
            Ps[tid][j] = p;
            ls += p;
        }
        l += ls;
        m = mnew;

        // P @ V (broadcast LDS reads)
        for (int j = 0; j < TK; j++) {
            float p = Ps[tid][j];
            const float4* vr = (const float4*)Vs[j];
            #pragma unroll
            for (int dd = 0; dd < 16; dd++) {
                float4 vv = vr[dd];
                acc[4*dd+0] += p * vv.x; acc[4*dd+1] += p * vv.y;
                acc[4*dd+2] += p * vv.z; acc[4*dd+3] += p * vv.w;
            }
        }
    }

    float inv = 1.f / l;
    float* op = o + ((size_t)(b * N_ + q)) * C_ + h * DH;
    #pragma unroll
    for (int dd = 0; dd < 16; dd++) {
        float4 v;
        v.x = acc[4*dd+0] * inv; v.y = acc[4*dd+1] * inv;
        v.z = acc[4*dd+2] * inv; v.w = acc[4*dd+3] * inv;
        *(float4*)(op + 4*dd) = v;
    }
}

// ---------------- launch ----------------------------------------------------
extern "C" void kernel_launch(void* const* d_in, const int* in_sizes, int n_in,
                              void* d_out, int out_size)
{
    const float* x      = (const float*)d_in[0];
    const float* qkv_w  = (const float*)d_in[1];
    const float* proj_w = (const float*)d_in[2];
    const float* proj_b = (const float*)d_in[3];
    const float* fc1_w  = (const float*)d_in[4];
    const float* fc1_b  = (const float*)d_in[5];
    const float* fc2_w  = (const float*)d_in[6];
    const float* fc2_b  = (const float*)d_in[7];
    const float* ln1_g  = (const float*)d_in[8];
    const float* ln1_b  = (const float*)d_in[9];
    const float* ln2_g  = (const float*)d_in[10];
    const float* ln2_b  = (const float*)d_in[11];
    const float* lnh_g  = (const float*)d_in[12];
    const float* lnh_b  = (const float*)d_in[13];
    float* out = (float*)d_out;

    float *h, *qkv, *o, *x1, *u;
    cudaGetSymbolAddress((void**)&h,   g_h);
    cudaGetSymbolAddress((void**)&qkv, g_qkv);
    cudaGetSymbolAddress((void**)&o,   g_o);
    cudaGetSymbolAddress((void**)&x1,  g_x1);
    cudaGetSymbolAddress((void**)&u,   g_u);

    // --- attention sublayer ---
    ln_kernel<<<R_, 256>>>(x, ln1_g, ln1_b, h, C_);
    sgemm_nt<0><<<dim3(3*C_/128, R_/128), 256>>>(h, qkv_w, qkv,
                                                 nullptr, nullptr, R_, 3*C_, C_);
    attn_kernel<<<dim3(N_/128, H_, B_), 128>>>(qkv, o);
    sgemm_nt<2><<<dim3(C_/128, R_/128), 256>>>(o, proj_w, x1,
                                               proj_b, x, R_, C_, C_);

    // --- MLP sublayer ---
    ln_kernel<<<R_, 256>>>(x1, ln2_g, ln2_b, h, C_);
    sgemm_nt<1><<<dim3(DHID/128, R_/128), 256>>>(h, fc1_w, u,
                                                 fc1_b, nullptr, R_, DHID, C_);
    ln_kernel<<<R_, 256>>>(u, lnh_g, lnh_b, u, DHID);   // in-place LN on hidden
    sgemm_nt<2><<<dim3(C_/128, R_/128), 256>>>(u, fc2_w, out,
                                               fc2_b, x1, R_, C_, DHID);
}

// round 2
// speedup vs baseline: 2.1471x; 2.1471x over previous
#include <cuda_runtime.h>
#include <math.h>
#include <stdint.h>

// Problem constants
#define B_    4
#define N_    1024
#define C_    1024
#define H_    16
#define DH    64
#define DHID  4096
#define R_    (B_*N_)   // 4096 token rows

// ---------------- scratch (device globals: allocation-guard safe) ----------
__device__ float g_h  [R_*C_];          // LN outputs (reused)
__device__ float g_qkv[R_*3*C_];
__device__ float g_o  [R_*C_];          // attention output, [B,N,C]
__device__ float g_x1 [R_*C_];          // residual after attention
__device__ float g_u  [R_*DHID];        // MLP hidden

// ---------------- small PTX helpers ----------------------------------------
__device__ __forceinline__ uint32_t smem_u32(const void* p){
    uint32_t a;
    asm("{ .reg .u64 t; cvta.to.shared.u64 t, %1; cvt.u32.u64 %0, t; }"
        : "=r"(a) : "l"(p));
    return a;
}
__device__ __forceinline__ void cp16(uint32_t dst, const float* src){
    asm volatile("cp.async.cg.shared.global [%0], [%1], 16;\n" :: "r"(dst), "l"(src));
}
__device__ __forceinline__ void cp_commit(){ asm volatile("cp.async.commit_group;\n"); }
template<int NN>
__device__ __forceinline__ void cp_wait(){ asm volatile("cp.async.wait_group %0;\n" :: "n"(NN)); }
__device__ __forceinline__ uint32_t f2tf(float x){
    uint32_t r; asm("cvt.rna.tf32.f32 %0, %1;" : "=r"(r) : "f"(x)); return r;
}
__device__ __forceinline__ void mma_tf32(float* d, const uint32_t* a, const uint32_t* b){
    asm volatile(
      "mma.sync.aligned.m16n8k8.row.col.f32.tf32.tf32.f32 "
      "{%0,%1,%2,%3}, {%4,%5,%6,%7}, {%8,%9}, {%0,%1,%2,%3};\n"
      : "+f"(d[0]), "+f"(d[1]), "+f"(d[2]), "+f"(d[3])
      : "r"(a[0]), "r"(a[1]), "r"(a[2]), "r"(a[3]), "r"(b[0]), "r"(b[1]));
}

// ---------------- LayerNorm: one block per row -----------------------------
__global__ void ln_kernel(const float* __restrict__ x,
                          const float* __restrict__ g,
                          const float* __restrict__ bb,
                          float* __restrict__ y, int C)
{
    int row = blockIdx.x;
    int tid = threadIdx.x;
    const float* xr = x + (size_t)row * C;
    float*       yr = y + (size_t)row * C;

    float s = 0.f, sq = 0.f;
    for (int i = tid * 4; i < C; i += 256 * 4) {
        float4 v = *(const float4*)(xr + i);
        s  += v.x + v.y + v.z + v.w;
        sq += v.x*v.x + v.y*v.y + v.z*v.z + v.w*v.w;
    }
    for (int o = 16; o > 0; o >>= 1) {
        s  += __shfl_xor_sync(0xffffffffu, s,  o);
        sq += __shfl_xor_sync(0xffffffffu, sq, o);
    }
    __shared__ float rs[8], rq[8], stats[2];
    int w = tid >> 5, ln = tid & 31;
    if (ln == 0) { rs[w] = s; rq[w] = sq; }
    __syncthreads();
    if (tid == 0) {
        float ts = 0.f, tq = 0.f;
        #pragma unroll
        for (int i = 0; i < 8; i++) { ts += rs[i]; tq += rq[i]; }
        float mu  = ts / (float)C;
        float var = tq / (float)C - mu * mu;
        stats[0] = mu;
        stats[1] = rsqrtf(var + 1e-5f);
    }
    __syncthreads();
    float mu = stats[0], r = stats[1];
    for (int i = tid * 4; i < C; i += 256 * 4) {
        float4 v  = *(const float4*)(xr + i);
        float4 gg = *(const float4*)(g  + i);
        float4 be = *(const float4*)(bb + i);
        float4 o4;
        o4.x = (v.x - mu) * r * gg.x + be.x;
        o4.y = (v.y - mu) * r * gg.y + be.y;
        o4.z = (v.z - mu) * r * gg.z + be.z;
        o4.w = (v.w - mu) * r * gg.w + be.w;
        *(float4*)(yr + i) = o4;
    }
}

// ---------------- TF32 tensor-core GEMM (NT): C = A[M,K] @ B[N,K]^T --------
// EPI: 0 = plain, 1 = +bias then erf-GELU, 2 = +bias +residual
// 128x128x32 tiles, 3-stage cp.async pipeline, XOR-swizzled smem,
// 8 warps in a 2x4 grid, warp tile 64x32 (4x4 m16n8k8 MMAs per k-step).
template<int EPI>
__global__ void __launch_bounds__(256)
gemm_tc(const float* __restrict__ A, const float* __restrict__ Bm,
        float* __restrict__ Cc, const float* __restrict__ bias,
        const float* __restrict__ res, int M, int Nn, int K)
{
    constexpr int BM = 128, BN = 128, BK = 32, ST = 3;
    extern __shared__ float sm[];
    float* As = sm;                    // ST * BM * BK
    float* Bs = sm + ST * BM * BK;     // ST * BN * BK

    const int tid  = threadIdx.x;
    const int warp = tid >> 5, lane = tid & 31;
    const int g    = lane >> 2, qd = lane & 3;
    const int wM   = warp >> 2, wN = warp & 3;           // 2 x 4 warp grid
    const int bM   = blockIdx.y * BM, bN = blockIdx.x * BN;
    const uint32_t sw = (uint32_t)(g << 2);              // per-thread XOR swizzle

    const uint32_t as_u = smem_u32(As);
    const uint32_t bs_u = smem_u32(Bs);

    float acc[4][4][4];
    #pragma unroll
    for (int i = 0; i < 4; i++)
        #pragma unroll
        for (int j = 0; j < 4; j++)
            #pragma unroll
            for (int e = 0; e < 4; e++) acc[i][j][e] = 0.f;

    const int KT = K / BK;

    auto load_stage = [&](int s, int k0) {
        #pragma unroll
        for (int i = 0; i < 4; i++) {
            int f4 = i * 256 + tid;              // 0..1023
            int r  = f4 >> 3;                    // 0..127
            int q  = f4 & 7;                     // 0..7
            uint32_t col = (uint32_t)(q * 4) ^ (uint32_t)((r & 7) << 2);
            cp16(as_u + (uint32_t)(s * BM * BK + r * BK + col) * 4u,
                 A + (size_t)(bM + r) * K + k0 + q * 4);
            cp16(bs_u + (uint32_t)(s * BN * BK + r * BK + col) * 4u,
                 Bm + (size_t)(bN + r) * K + k0 + q * 4);
        }
        cp_commit();
    };

    // prologue: stages 0..ST-2
    #pragma unroll
    for (int s = 0; s < ST - 1; s++) load_stage(s, s * BK);

    for (int t = 0; t < KT; t++) {
        cp_wait<ST - 2>();
        __syncthreads();

        int tn = t + ST - 1;
        if (tn < KT) load_stage(tn % ST, tn * BK);
        else         cp_commit();                 // keep group count aligned

        const float* a_st = As + (t % ST) * BM * BK;
        const float* b_st = Bs + (t % ST) * BN * BK;

        #pragma unroll
        for (int kk = 0; kk < 4; kk++) {
            const int k0 = kk * 8 + qd, k1 = k0 + 4;
            uint32_t af[4][4], bf[4][2];
            #pragma unroll
            for (int i = 0; i < 4; i++) {
                int m0 = wM * 64 + i * 16 + g;
                int m1 = m0 + 8;
                af[i][0] = f2tf(a_st[m0 * BK + ((uint32_t)k0 ^ sw)]);
                af[i][1] = f2tf(a_st[m1 * BK + ((uint32_t)k0 ^ sw)]);
                af[i][2] = f2tf(a_st[m0 * BK + ((uint32_t)k1 ^ sw)]);
                af[i][3] = f2tf(a_st[m1 * BK + ((uint32_t)k1 ^ sw)]);
            }
            #pragma unroll
            for (int j = 0; j < 4; j++) {
                int n0 = wN * 32 + j * 8 + g;
                bf[j][0] = f2tf(b_st[n0 * BK + ((uint32_t)k0 ^ sw)]);
                bf[j][1] = f2tf(b_st[n0 * BK + ((uint32_t)k1 ^ sw)]);
            }
            #pragma unroll
            for (int i = 0; i < 4; i++)
                #pragma unroll
                for (int j = 0; j < 4; j++)
                    mma_tf32(acc[i][j], af[i], bf[j]);
        }
    }

    // epilogue
    #pragma unroll
    for (int i = 0; i < 4; i++) {
        #pragma unroll
        for (int j = 0; j < 4; j++) {
            int r0 = bM + wM * 64 + i * 16 + g;
            int c0 = bN + wN * 32 + j * 8 + qd * 2;
            #pragma unroll
            for (int h = 0; h < 2; h++) {
                int r = r0 + h * 8;
                float v0 = acc[i][j][h * 2 + 0];
                float v1 = acc[i][j][h * 2 + 1];
                if (EPI >= 1) { v0 += bias[c0]; v1 += bias[c0 + 1]; }
                if (EPI == 1) {
                    v0 = 0.5f * v0 * (1.f + erff(v0 * 0.70710678118654752f));
                    v1 = 0.5f * v1 * (1.f + erff(v1 * 0.70710678118654752f));
                }
                if (EPI == 2) {
                    const float2 rr = *(const float2*)(res + (size_t)r * Nn + c0);
                    v0 += rr.x; v1 += rr.y;
                }
                float2 o2; o2.x = v0; o2.y = v1;
                *(float2*)(Cc + (size_t)r * Nn + c0) = o2;
            }
        }
    }
}

// ---------------- Flash attention (fp32, online softmax) -------------------
__global__ void __launch_bounds__(128)
attn_kernel(const float* __restrict__ qkv, float* __restrict__ o)
{
    constexpr int TQ = 128, TK = 32, D = 64;
    __shared__ float Ks[TK][D];
    __shared__ float Vs[TK][D];
    __shared__ float Ps[TQ][TK + 1];

    int tid = threadIdx.x;
    int b = blockIdx.z, h = blockIdx.y;
    int q = blockIdx.x * TQ + tid;
    const int RS = 3 * C_;

    const float* qp = qkv + ((size_t)(b * N_ + q)) * RS + h * DH;
    float qv[D];
    #pragma unroll
    for (int dd = 0; dd < 16; dd++)
        *(float4*)(qv + 4*dd) = *(const float4*)(qp + 4*dd);

    float acc[D] = {};
    float m = -1e30f, l = 0.f;
    const float scale = 0.125f;

    for (int t = 0; t < N_ / TK; t++) {
        __syncthreads();
        for (int i = tid; i < TK * 16; i += TQ) {
            int key = i >> 4, dd = i & 15;
            const float* base = qkv + ((size_t)(b * N_ + t * TK + key)) * RS + h * DH;
            *(float4*)&Ks[key][dd*4] = *(const float4*)(base + C_   + dd*4);
            *(float4*)&Vs[key][dd*4] = *(const float4*)(base + 2*C_ + dd*4);
        }
        __syncthreads();

        float tmax = -1e30f;
        for (int j = 0; j < TK; j++) {
            float s = 0.f;
            const float4* kr = (const float4*)Ks[j];
            #pragma unroll
            for (int dd = 0; dd < 16; dd++) {
                float4 kv = kr[dd];
                s += qv[4*dd+0]*kv.x + qv[4*dd+1]*kv.y
                   + qv[4*dd+2]*kv.z + qv[4*dd+3]*kv.w;
            }
            s *= scale;
            Ps[tid][j] = s;
            tmax = fmaxf(tmax, s);
        }

        float mnew = fmaxf(m, tmax);
        float corr = __expf(m - mnew);
        l *= corr;
        #pragma unroll
        for (int d = 0; d < D; d++) acc[d] *= corr;
        float ls = 0.f;
        for (int j = 0; j < TK; j++) {
            float p = __expf(Ps[tid][j] - mnew);
            Ps[tid][j] = p;
            ls += p;
        }
        l += ls;
        m = mnew;

        for (int j = 0; j < TK; j++) {
            float p = Ps[tid][j];
            const float4* vr = (const float4*)Vs[j];
            #pragma unroll
            for (int dd = 0; dd < 16; dd++) {
                float4 vv = vr[dd];
                acc[4*dd+0] += p * vv.x; acc[4*dd+1] += p * vv.y;
                acc[4*dd+2] += p * vv.z; acc[4*dd+3] += p * vv.w;
            }
        }
    }

    float inv = 1.f / l;
    float* op = o + ((size_t)(b * N_ + q)) * C_ + h * DH;
    #pragma unroll
    for (int dd = 0; dd < 16; dd++) {
        float4 v;
        v.x = acc[4*dd+0] * inv; v.y = acc[4*dd+1] * inv;
        v.z = acc[4*dd+2] * inv; v.w = acc[4*dd+3] * inv;
        *(float4*)(op + 4*dd) = v;
    }
}

// ---------------- launch ----------------------------------------------------
extern "C" void kernel_launch(void* const* d_in, const int* in_sizes, int n_in,
                              void* d_out, int out_size)
{
    const float* x      = (const float*)d_in[0];
    const float* qkv_w  = (const float*)d_in[1];
    const float* proj_w = (const float*)d_in[2];
    const float* proj_b = (const float*)d_in[3];
    const float* fc1_w  = (const float*)d_in[4];
    const float* fc1_b  = (const float*)d_in[5];
    const float* fc2_w  = (const float*)d_in[6];
    const float* fc2_b  = (const float*)d_in[7];
    const float* ln1_g  = (const float*)d_in[8];
    const float* ln1_b  = (const float*)d_in[9];
    const float* ln2_g  = (const float*)d_in[10];
    const float* ln2_b  = (const float*)d_in[11];
    const float* lnh_g  = (const float*)d_in[12];
    const float* lnh_b  = (const float*)d_in[13];
    float* out = (float*)d_out;

    float *h, *qkv, *o, *x1, *u;
    cudaGetSymbolAddress((void**)&h,   g_h);
    cudaGetSymbolAddress((void**)&qkv, g_qkv);
    cudaGetSymbolAddress((void**)&o,   g_o);
    cudaGetSymbolAddress((void**)&x1,  g_x1);
    cudaGetSymbolAddress((void**)&u,   g_u);

    const int SMEM = 3 * (128 + 128) * 32 * 4;   // 96 KB dynamic
    cudaFuncSetAttribute(gemm_tc<0>, cudaFuncAttributeMaxDynamicSharedMemorySize, SMEM);
    cudaFuncSetAttribute(gemm_tc<1>, cudaFuncAttributeMaxDynamicSharedMemorySize, SMEM);
    cudaFuncSetAttribute(gemm_tc<2>, cudaFuncAttributeMaxDynamicSharedMemorySize, SMEM);

    // --- attention sublayer ---
    ln_kernel<<<R_, 256>>>(x, ln1_g, ln1_b, h, C_);
    gemm_tc<0><<<dim3(3*C_/128, R_/128), 256, SMEM>>>(h, qkv_w, qkv,
                                                      nullptr, nullptr, R_, 3*C_, C_);
    attn_kernel<<<dim3(N_/128, H_, B_), 128>>>(qkv, o);
    gemm_tc<2><<<dim3(C_/128, R_/128), 256, SMEM>>>(o, proj_w, x1,
                                                    proj_b, x, R_, C_, C_);

    // --- MLP sublayer ---
    ln_kernel<<<R_, 256>>>(x1, ln2_g, ln2_b, h, C_);
    gemm_tc<1><<<dim3(DHID/128, R_/128), 256, SMEM>>>(h, fc1_w, u,
                                                      fc1_b, nullptr, R_, DHID, C_);
    ln_kernel<<<R_, 256>>>(u, lnh_g, lnh_b, u, DHID);
    gemm_tc<2><<<dim3(C_/128, R_/128), 256, SMEM>>>(u, fc2_w, out,
                                                    fc2_b, x1, R_, C_, DHID);
}

// round 3
// speedup vs baseline: 3.4677x; 1.6151x over previous
#include <cuda_runtime.h>
#include <math.h>
#include <stdint.h>

// Problem constants
#define B_    4
#define N_    1024
#define C_    1024
#define H_    16
#define DH    64
#define DHID  4096
#define R_    (B_*N_)   // 4096 token rows

// ---------------- scratch (device globals: allocation-guard safe) ----------
__device__ float g_h  [R_*C_];          // LN outputs (tf32-rounded)
__device__ float g_qkv[R_*3*C_];        // tf32-rounded
__device__ float g_o  [R_*C_];          // attention output (tf32-rounded)
__device__ float g_x1 [R_*C_];          // residual after attention (fp32)
__device__ float g_u  [R_*DHID];        // MLP hidden
// tf32-rounded weight copies
__device__ float g_wq [3*C_*C_];
__device__ float g_wp [C_*C_];
__device__ float g_w1 [DHID*C_];
__device__ float g_w2 [C_*DHID];

// ---------------- small PTX helpers ----------------------------------------
__device__ __forceinline__ uint32_t smem_u32(const void* p){
    uint32_t a;
    asm("{ .reg .u64 t; cvta.to.shared.u64 t, %1; cvt.u32.u64 %0, t; }"
        : "=r"(a) : "l"(p));
    return a;
}
__device__ __forceinline__ void cp16(uint32_t dst, const float* src){
    asm volatile("cp.async.cg.shared.global [%0], [%1], 16;\n" :: "r"(dst), "l"(src));
}
__device__ __forceinline__ void cp_commit(){ asm volatile("cp.async.commit_group;\n"); }
template<int NN>
__device__ __forceinline__ void cp_wait(){ asm volatile("cp.async.wait_group %0;\n" :: "n"(NN)); }
__device__ __forceinline__ float f2tf_f(float x){
    uint32_t r; asm("cvt.rna.tf32.f32 %0, %1;" : "=r"(r) : "f"(x));
    return __uint_as_float(r);
}
__device__ __forceinline__ void mma_tf32(float* d, const uint32_t* a, const uint32_t* b){
    asm volatile(
      "mma.sync.aligned.m16n8k8.row.col.f32.tf32.tf32.f32 "
      "{%0,%1,%2,%3}, {%4,%5,%6,%7}, {%8,%9}, {%0,%1,%2,%3};\n"
      : "+f"(d[0]), "+f"(d[1]), "+f"(d[2]), "+f"(d[3])
      : "r"(a[0]), "r"(a[1]), "r"(a[2]), "r"(a[3]), "r"(b[0]), "r"(b[1]));
}

// ---------------- tf32 rounding pass (weights) ------------------------------
__global__ void round_tf32_kernel(const float* __restrict__ src,
                                  float* __restrict__ dst, int n4)
{
    int i = blockIdx.x * 256 + threadIdx.x;
    if (i < n4) {
        float4 v = ((const float4*)src)[i];
        v.x = f2tf_f(v.x); v.y = f2tf_f(v.y);
        v.z = f2tf_f(v.z); v.w = f2tf_f(v.w);
        ((float4*)dst)[i] = v;
    }
}

// ---------------- LayerNorm: one block per row -----------------------------
template<bool RND>
__global__ void ln_kernel(const float* __restrict__ x,
                          const float* __restrict__ g,
                          const float* __restrict__ bb,
                          float* __restrict__ y, int C)
{
    int row = blockIdx.x;
    int tid = threadIdx.x;
    const float* xr = x + (size_t)row * C;
    float*       yr = y + (size_t)row * C;

    float s = 0.f, sq = 0.f;
    for (int i = tid * 4; i < C; i += 256 * 4) {
        float4 v = *(const float4*)(xr + i);
        s  += v.x + v.y + v.z + v.w;
        sq += v.x*v.x + v.y*v.y + v.z*v.z + v.w*v.w;
    }
    for (int o = 16; o > 0; o >>= 1) {
        s  += __shfl_xor_sync(0xffffffffu, s,  o);
        sq += __shfl_xor_sync(0xffffffffu, sq, o);
    }
    __shared__ float rs[8], rq[8], stats[2];
    int w = tid >> 5, ln = tid & 31;
    if (ln == 0) { rs[w] = s; rq[w] = sq; }
    __syncthreads();
    if (tid == 0) {
        float ts = 0.f, tq = 0.f;
        #pragma unroll
        for (int i = 0; i < 8; i++) { ts += rs[i]; tq += rq[i]; }
        float mu  = ts / (float)C;
        float var = tq / (float)C - mu * mu;
        stats[0] = mu;
        stats[1] = rsqrtf(var + 1e-5f);
    }
    __syncthreads();
    float mu = stats[0], r = stats[1];
    for (int i = tid * 4; i < C; i += 256 * 4) {
        float4 v  = *(const float4*)(xr + i);
        float4 gg = *(const float4*)(g  + i);
        float4 be = *(const float4*)(bb + i);
        float4 o4;
        o4.x = (v.x - mu) * r * gg.x + be.x;
        o4.y = (v.y - mu) * r * gg.y + be.y;
        o4.z = (v.z - mu) * r * gg.z + be.z;
        o4.w = (v.w - mu) * r * gg.w + be.w;
        if (RND) {
            o4.x = f2tf_f(o4.x); o4.y = f2tf_f(o4.y);
            o4.z = f2tf_f(o4.z); o4.w = f2tf_f(o4.w);
        }
        *(float4*)(yr + i) = o4;
    }
}

// ---------------- TF32 tensor-core GEMM (NT): C = A[M,K] @ B[N,K]^T --------
// Inputs must be pre-rounded to tf32. EPI: 0 plain, 1 +bias+erfGELU, 2 +bias+res
template<int EPI, bool RND>
__global__ void __launch_bounds__(256)
gemm_tc(const float* __restrict__ A, const float* __restrict__ Bm,
        float* __restrict__ Cc, const float* __restrict__ bias,
        const float* __restrict__ res, int M, int Nn, int K)
{
    constexpr int BM = 128, BN = 128, BK = 32, ST = 3;
    extern __shared__ float sm[];
    float* As = sm;
    float* Bs = sm + ST * BM * BK;

    const int tid  = threadIdx.x;
    const int warp = tid >> 5, lane = tid & 31;
    const int g    = lane >> 2, qd = lane & 3;
    const int wM   = warp >> 2, wN = warp & 3;
    const int bM   = blockIdx.y * BM, bN = blockIdx.x * BN;
    const uint32_t sw = (uint32_t)(g << 2);

    const uint32_t as_u = smem_u32(As);
    const uint32_t bs_u = smem_u32(Bs);

    float acc[4][4][4];
    #pragma unroll
    for (int i = 0; i < 4; i++)
        #pragma unroll
        for (int j = 0; j < 4; j++)
            #pragma unroll
            for (int e = 0; e < 4; e++) acc[i][j][e] = 0.f;

    const int KT = K / BK;

    auto load_stage = [&](int s, int k0) {
        #pragma unroll
        for (int i = 0; i < 4; i++) {
            int f4 = i * 256 + tid;
            int r  = f4 >> 3;
            int q  = f4 & 7;
            uint32_t col = (uint32_t)(q * 4) ^ (uint32_t)((r & 7) << 2);
            cp16(as_u + (uint32_t)(s * BM * BK + r * BK + col) * 4u,
                 A + (size_t)(bM + r) * K + k0 + q * 4);
            cp16(bs_u + (uint32_t)(s * BN * BK + r * BK + col) * 4u,
                 Bm + (size_t)(bN + r) * K + k0 + q * 4);
        }
        cp_commit();
    };

    #pragma unroll
    for (int s = 0; s < ST - 1; s++) load_stage(s, s * BK);

    for (int t = 0; t < KT; t++) {
        cp_wait<ST - 2>();
        __syncthreads();

        int tn = t + ST - 1;
        if (tn < KT) load_stage(tn % ST, tn * BK);
        else         cp_commit();

        const float* a_st = As + (t % ST) * BM * BK;
        const float* b_st = Bs + (t % ST) * BN * BK;

        #pragma unroll
        for (int kk = 0; kk < 4; kk++) {
            const int k0 = kk * 8 + qd, k1 = k0 + 4;
            uint32_t af[4][4], bf[4][2];
            #pragma unroll
            for (int i = 0; i < 4; i++) {
                int m0 = wM * 64 + i * 16 + g;
                int m1 = m0 + 8;
                af[i][0] = __float_as_uint(a_st[m0 * BK + ((uint32_t)k0 ^ sw)]);
                af[i][1] = __float_as_uint(a_st[m1 * BK + ((uint32_t)k0 ^ sw)]);
                af[i][2] = __float_as_uint(a_st[m0 * BK + ((uint32_t)k1 ^ sw)]);
                af[i][3] = __float_as_uint(a_st[m1 * BK + ((uint32_t)k1 ^ sw)]);
            }
            #pragma unroll
            for (int j = 0; j < 4; j++) {
                int n0 = wN * 32 + j * 8 + g;
                bf[j][0] = __float_as_uint(b_st[n0 * BK + ((uint32_t)k0 ^ sw)]);
                bf[j][1] = __float_as_uint(b_st[n0 * BK + ((uint32_t)k1 ^ sw)]);
            }
            #pragma unroll
            for (int i = 0; i < 4; i++)
                #pragma unroll
                for (int j = 0; j < 4; j++)
                    mma_tf32(acc[i][j], af[i], bf[j]);
        }
    }

    #pragma unroll
    for (int i = 0; i < 4; i++) {
        #pragma unroll
        for (int j = 0; j < 4; j++) {
            int r0 = bM + wM * 64 + i * 16 + g;
            int c0 = bN + wN * 32 + j * 8 + qd * 2;
            #pragma unroll
            for (int h = 0; h < 2; h++) {
                int r = r0 + h * 8;
                float v0 = acc[i][j][h * 2 + 0];
                float v1 = acc[i][j][h * 2 + 1];
                if (EPI >= 1) { v0 += bias[c0]; v1 += bias[c0 + 1]; }
                if (EPI == 1) {
                    v0 = 0.5f * v0 * (1.f + erff(v0 * 0.70710678118654752f));
                    v1 = 0.5f * v1 * (1.f + erff(v1 * 0.70710678118654752f));
                }
                if (EPI == 2) {
                    const float2 rr = *(const float2*)(res + (size_t)r * Nn + c0);
                    v0 += rr.x; v1 += rr.y;
                }
                if (RND) { v0 = f2tf_f(v0); v1 = f2tf_f(v1); }
                float2 o2; o2.x = v0; o2.y = v1;
                *(float2*)(Cc + (size_t)r * Nn + c0) = o2;
            }
        }
    }
}

// ---------------- Tensor-core flash attention --------------------------------
__global__ void __launch_bounds__(256)
attn_mma(const float* __restrict__ qkv, float* __restrict__ o)
{
    __shared__ float Ks[64][68];     // [key j][dim d]
    __shared__ float Vt[64][68];     // [dim d][key j]
    __shared__ float Ps[128][68];    // P tile; also Q staging

    const int tid  = threadIdx.x;
    const int warp = tid >> 5, lane = tid & 31;
    const int g    = lane >> 2, qd = lane & 3;
    const int wr   = warp * 16;
    const int b = blockIdx.z, h = blockIdx.y;
    const int q0 = blockIdx.x * 128;
    const int RS = 3 * C_;

    for (int i = tid; i < 128 * 16; i += 256) {
        int r = i >> 4, d4 = (i & 15) * 4;
        *(float4*)&Ps[r][d4] =
            *(const float4*)(qkv + (size_t)(b * N_ + q0 + r) * RS + h * DH + d4);
    }
    __syncthreads();

    uint32_t qf[8][4];
    #pragma unroll
    for (int kk = 0; kk < 8; kk++) {
        qf[kk][0] = __float_as_uint(Ps[wr + g    ][kk*8 + qd    ] * 0.125f);
        qf[kk][1] = __float_as_uint(Ps[wr + g + 8][kk*8 + qd    ] * 0.125f);
        qf[kk][2] = __float_as_uint(Ps[wr + g    ][kk*8 + qd + 4] * 0.125f);
        qf[kk][3] = __float_as_uint(Ps[wr + g + 8][kk*8 + qd + 4] * 0.125f);
    }

    float oacc[8][4];
    #pragma unroll
    for (int nb = 0; nb < 8; nb++)
        #pragma unroll
        for (int e = 0; e < 4; e++) oacc[nb][e] = 0.f;
    float m0 = -1e30f, m1 = -1e30f, l0 = 0.f, l1 = 0.f;

    for (int t = 0; t < N_ / 64; t++) {
        __syncthreads();
        for (int i = tid; i < 64 * 16; i += 256) {
            int j = i >> 4, d4 = (i & 15) * 4;
            const float* base = qkv + (size_t)(b * N_ + t * 64 + j) * RS + h * DH + d4;
            *(float4*)&Ks[j][d4] = *(const float4*)(base + C_);
            float4 v = *(const float4*)(base + 2 * C_);
            Vt[d4 + 0][j] = v.x; Vt[d4 + 1][j] = v.y;
            Vt[d4 + 2][j] = v.z; Vt[d4 + 3][j] = v.w;
        }
        __syncthreads();

        float sacc[8][4];
        #pragma unroll
        for (int nb = 0; nb < 8; nb++)
            #pragma unroll
            for (int e = 0; e < 4; e++) sacc[nb][e] = 0.f;
        #pragma unroll
        for (int kk = 0; kk < 8; kk++) {
            uint32_t bf[8][2];
            #pragma unroll
            for (int nb = 0; nb < 8; nb++) {
                bf[nb][0] = __float_as_uint(Ks[nb*8 + g][kk*8 + qd    ]);
                bf[nb][1] = __float_as_uint(Ks[nb*8 + g][kk*8 + qd + 4]);
            }
            #pragma unroll
            for (int nb = 0; nb < 8; nb++) mma_tf32(sacc[nb], qf[kk], bf[nb]);
        }

        float mx0 = -1e30f, mx1 = -1e30f;
        #pragma unroll
        for (int nb = 0; nb < 8; nb++) {
            mx0 = fmaxf(mx0, fmaxf(sacc[nb][0], sacc[nb][1]));
            mx1 = fmaxf(mx1, fmaxf(sacc[nb][2], sacc[nb][3]));
        }
        mx0 = fmaxf(mx0, __shfl_xor_sync(0xffffffffu, mx0, 1));
        mx0 = fmaxf(mx0, __shfl_xor_sync(0xffffffffu, mx0, 2));
        mx1 = fmaxf(mx1, __shfl_xor_sync(0xffffffffu, mx1, 1));
        mx1 = fmaxf(mx1, __shfl_xor_sync(0xffffffffu, mx1, 2));

        float mn0 = fmaxf(m0, mx0), mn1 = fmaxf(m1, mx1);
        float c0 = __expf(m0 - mn0), c1 = __expf(m1 - mn1);
        float s0 = 0.f, s1 = 0.f;
        #pragma unroll
        for (int nb = 0; nb < 8; nb++) {
            float p00 = __expf(sacc[nb][0] - mn0);
            float p01 = __expf(sacc[nb][1] - mn0);
            float p10 = __expf(sacc[nb][2] - mn1);
            float p11 = __expf(sacc[nb][3] - mn1);
            s0 += p00 + p01;  s1 += p10 + p11;
            int c = nb * 8 + qd * 2;
            Ps[wr + g    ][c    ] = f2tf_f(p00);
            Ps[wr + g    ][c + 1] = f2tf_f(p01);
            Ps[wr + g + 8][c    ] = f2tf_f(p10);
            Ps[wr + g + 8][c + 1] = f2tf_f(p11);
        }
        s0 += __shfl_xor_sync(0xffffffffu, s0, 1);
        s0 += __shfl_xor_sync(0xffffffffu, s0, 2);
        s1 += __shfl_xor_sync(0xffffffffu, s1, 1);
        s1 += __shfl_xor_sync(0xffffffffu, s1, 2);
        l0 = l0 * c0 + s0;  l1 = l1 * c1 + s1;
        m0 = mn0;  m1 = mn1;
        #pragma unroll
        for (int nb = 0; nb < 8; nb++) {
            oacc[nb][0] *= c0; oacc[nb][1] *= c0;
            oacc[nb][2] *= c1; oacc[nb][3] *= c1;
        }
        __syncwarp();

        #pragma unroll
        for (int kk = 0; kk < 8; kk++) {
            uint32_t af[4];
            af[0] = __float_as_uint(Ps[wr + g    ][kk*8 + qd    ]);
            af[1] = __float_as_uint(Ps[wr + g + 8][kk*8 + qd    ]);
            af[2] = __float_as_uint(Ps[wr + g    ][kk*8 + qd + 4]);
            af[3] = __float_as_uint(Ps[wr + g + 8][kk*8 + qd + 4]);
            uint32_t bf[8][2];
            #pragma unroll
            for (int nb = 0; nb < 8; nb++) {
                bf[nb][0] = __float_as_uint(Vt[nb*8 + g][kk*8 + qd    ]);
                bf[nb][1] = __float_as_uint(Vt[nb*8 + g][kk*8 + qd + 4]);
            }
            #pragma unroll
            for (int nb = 0; nb < 8; nb++) mma_tf32(oacc[nb], af, bf[nb]);
        }
    }

    float i0 = 1.f / l0, i1 = 1.f / l1;
    float* op0 = o + (size_t)(b * N_ + q0 + wr + g    ) * C_ + h * DH;
    float* op1 = o + (size_t)(b * N_ + q0 + wr + g + 8) * C_ + h * DH;
    #pragma unroll
    for (int nb = 0; nb < 8; nb++) {
        int c = nb * 8 + qd * 2;
        float2 a, bb2;
        a.x   = f2tf_f(oacc[nb][0] * i0);  a.y   = f2tf_f(oacc[nb][1] * i0);
        bb2.x = f2tf_f(oacc[nb][2] * i1);  bb2.y = f2tf_f(oacc[nb][3] * i1);
        *(float2*)(op0 + c) = a;
        *(float2*)(op1 + c) = bb2;
    }
}

// ---------------- launch ----------------------------------------------------
extern "C" void kernel_launch(void* const* d_in, const int* in_sizes, int n_in,
                              void* d_out, int out_size)
{
    const float* x      = (const float*)d_in[0];
    const float* qkv_w  = (const float*)d_in[1];
    const float* proj_w = (const float*)d_in[2];
    const float* proj_b = (const float*)d_in[3];
    const float* fc1_w  = (const float*)d_in[4];
    const float* fc1_b  = (const float*)d_in[5];
    const float* fc2_w  = (const float*)d_in[6];
    const float* fc2_b  = (const float*)d_in[7];
    const float* ln1_g  = (const float*)d_in[8];
    const float* ln1_b  = (const float*)d_in[9];
    const float* ln2_g  = (const float*)d_in[10];
    const float* ln2_b  = (const float*)d_in[11];
    const float* lnh_g  = (const float*)d_in[12];
    const float* lnh_b  = (const float*)d_in[13];
    float* out = (float*)d_out;

    float *h, *qkv, *o, *x1, *u, *wq, *wp, *w1, *w2;
    cudaGetSymbolAddress((void**)&h,   g_h);
    cudaGetSymbolAddress((void**)&qkv, g_qkv);
    cudaGetSymbolAddress((void**)&o,   g_o);
    cudaGetSymbolAddress((void**)&x1,  g_x1);
    cudaGetSymbolAddress((void**)&u,   g_u);
    cudaGetSymbolAddress((void**)&wq,  g_wq);
    cudaGetSymbolAddress((void**)&wp,  g_wp);
    cudaGetSymbolAddress((void**)&w1,  g_w1);
    cudaGetSymbolAddress((void**)&w2,  g_w2);

    const int SMEM = 3 * (128 + 128) * 32 * 4;   // 96 KB dynamic
    cudaFuncSetAttribute(gemm_tc<0,true >, cudaFuncAttributeMaxDynamicSharedMemorySize, SMEM);
    cudaFuncSetAttribute(gemm_tc<1,false>, cudaFuncAttributeMaxDynamicSharedMemorySize, SMEM);
    cudaFuncSetAttribute(gemm_tc<2,false>, cudaFuncAttributeMaxDynamicSharedMemorySize, SMEM);

    round_tf32_kernel<<<(3*C_*C_/4 + 255)/256, 256>>>(qkv_w,  wq, 3*C_*C_/4);
    round_tf32_kernel<<<(C_*C_/4   + 255)/256, 256>>>(proj_w, wp, C_*C_/4);
    round_tf32_kernel<<<(DHID*C_/4 + 255)/256, 256>>>(fc1_w,  w1, DHID*C_/4);
    round_tf32_kernel<<<(C_*DHID/4 + 255)/256, 256>>>(fc2_w,  w2, C_*DHID/4);

    ln_kernel<true><<<R_, 256>>>(x, ln1_g, ln1_b, h, C_);
    gemm_tc<0,true><<<dim3(3*C_/128, R_/128), 256, SMEM>>>(h, wq, qkv,
                                                  nullptr, nullptr, R_, 3*C_, C_);
    attn_mma<<<dim3(N_/128, H_, B_), 256>>>(qkv, o);
    gemm_tc<2,false><<<dim3(C_/128, R_/128), 256, SMEM>>>(o, wp, x1,
                                                  proj_b, x, R_, C_, C_);

    ln_kernel<true><<<R_, 256>>>(x1, ln2_g, ln2_b, h, C_);
    gemm_tc<1,false><<<dim3(DHID/128, R_/128), 256, SMEM>>>(h, w1, u,
                                                  fc1_b, nullptr, R_, DHID, C_);
    ln_kernel<true><<<R_, 256>>>(u, lnh_g, lnh_b, u, DHID);
    gemm_tc<2,false><<<dim3(C_/128, R_/128), 256, SMEM>>>(u, w2, out,
                                                  fc2_b, x1, R_, C_, DHID);
}

// round 5
// speedup vs baseline: 3.9011x; 1.1250x over previous
#include <cuda_runtime.h>
#include <math.h>
#include <stdint.h>

// Problem constants
#define B_    4
#define N_    1024
#define C_    1024
#define H_    16
#define DH    64
#define DHID  4096
#define R_    (B_*N_)   // 4096 token rows

// ---------------- scratch (device globals: allocation-guard safe) ----------
__device__ float g_h  [R_*C_];          // LN outputs (tf32-rounded)
__device__ float g_qkv[R_*3*C_];        // tf32-rounded
__device__ float g_o  [R_*C_];          // attention output (tf32-rounded)
__device__ float g_x1 [R_*C_];          // residual after attention (fp32)
__device__ float g_u  [R_*DHID];        // MLP hidden
// tf32-rounded weight copies
__device__ float g_wq [3*C_*C_];
__device__ float g_wp [C_*C_];
__device__ float g_w1 [DHID*C_];
__device__ float g_w2 [C_*DHID];

// ---------------- PTX helpers ----------------------------------------------
__device__ __forceinline__ uint32_t smem_u32(const void* p){
    uint32_t a;
    asm("{ .reg .u64 t; cvta.to.shared.u64 t, %1; cvt.u32.u64 %0, t; }"
        : "=r"(a) : "l"(p));
    return a;
}
__device__ __forceinline__ void cp16(uint32_t dst, const float* src){
    asm volatile("cp.async.cg.shared.global [%0], [%1], 16;\n" :: "r"(dst), "l"(src));
}
__device__ __forceinline__ void cp_commit(){ asm volatile("cp.async.commit_group;\n"); }
template<int NN>
__device__ __forceinline__ void cp_wait(){ asm volatile("cp.async.wait_group %0;\n" :: "n"(NN)); }
__device__ __forceinline__ float f2tf_f(float x){
    uint32_t r; asm("cvt.rna.tf32.f32 %0, %1;" : "=r"(r) : "f"(x));
    return __uint_as_float(r);
}
__device__ __forceinline__ void mma_tf32(float* d, const uint32_t* a, const uint32_t* b){
    asm volatile(
      "mma.sync.aligned.m16n8k8.row.col.f32.tf32.tf32.f32 "
      "{%0,%1,%2,%3}, {%4,%5,%6,%7}, {%8,%9}, {%0,%1,%2,%3};\n"
      : "+f"(d[0]), "+f"(d[1]), "+f"(d[2]), "+f"(d[3])
      : "r"(a[0]), "r"(a[1]), "r"(a[2]), "r"(a[3]), "r"(b[0]), "r"(b[1]));
}

// ---------------- tf32 rounding pass (weights) ------------------------------
__global__ void round_tf32_kernel(const float* __restrict__ src,
                                  float* __restrict__ dst, int n4)
{
    int i = blockIdx.x * 256 + threadIdx.x;
    if (i < n4) {
        float4 v = ((const float4*)src)[i];
        v.x = f2tf_f(v.x); v.y = f2tf_f(v.y);
        v.z = f2tf_f(v.z); v.w = f2tf_f(v.w);
        ((float4*)dst)[i] = v;
    }
}

// ---------------- LayerNorm: one block per row -----------------------------
template<bool RND>
__global__ void ln_kernel(const float* __restrict__ x,
                          const float* __restrict__ g,
                          const float* __restrict__ bb,
                          float* __restrict__ y, int C)
{
    int row = blockIdx.x;
    int tid = threadIdx.x;
    const float* xr = x + (size_t)row * C;
    float*       yr = y + (size_t)row * C;

    float s = 0.f, sq = 0.f;
    for (int i = tid * 4; i < C; i += 256 * 4) {
        float4 v = *(const float4*)(xr + i);
        s  += v.x + v.y + v.z + v.w;
        sq += v.x*v.x + v.y*v.y + v.z*v.z + v.w*v.w;
    }
    for (int o = 16; o > 0; o >>= 1) {
        s  += __shfl_xor_sync(0xffffffffu, s,  o);
        sq += __shfl_xor_sync(0xffffffffu, sq, o);
    }
    __shared__ float rs[8], rq[8], stats[2];
    int w = tid >> 5, ln = tid & 31;
    if (ln == 0) { rs[w] = s; rq[w] = sq; }
    __syncthreads();
    if (tid == 0) {
        float ts = 0.f, tq = 0.f;
        #pragma unroll
        for (int i = 0; i < 8; i++) { ts += rs[i]; tq += rq[i]; }
        float mu  = ts / (float)C;
        float var = tq / (float)C - mu * mu;
        stats[0] = mu;
        stats[1] = rsqrtf(var + 1e-5f);
    }
    __syncthreads();
    float mu = stats[0], r = stats[1];
    for (int i = tid * 4; i < C; i += 256 * 4) {
        float4 v  = *(const float4*)(xr + i);
        float4 gg = *(const float4*)(g  + i);
        float4 be = *(const float4*)(bb + i);
        float4 o4;
        o4.x = (v.x - mu) * r * gg.x + be.x;
        o4.y = (v.y - mu) * r * gg.y + be.y;
        o4.z = (v.z - mu) * r * gg.z + be.z;
        o4.w = (v.w - mu) * r * gg.w + be.w;
        if (RND) {
            o4.x = f2tf_f(o4.x); o4.y = f2tf_f(o4.y);
            o4.z = f2tf_f(o4.z); o4.w = f2tf_f(o4.w);
        }
        *(float4*)(yr + i) = o4;
    }
}

// ---------------- TF32 tensor-core GEMM (NT): C = A[M,K] @ B[N,K]^T --------
// Inputs pre-rounded to tf32. EPI: 0 plain, 1 +bias+erfGELU, 2 +bias+res
// 128x128x32 tiles, 3-stage cp.async pipeline, 2 CTAs/SM.
template<int EPI, bool RND>
__global__ void __launch_bounds__(256, 2)
gemm_tc(const float* __restrict__ A, const float* __restrict__ Bm,
        float* __restrict__ Cc, const float* __restrict__ bias,
        const float* __restrict__ res, int M, int Nn, int K)
{
    constexpr int BM = 128, BN = 128, BK = 32, ST = 3;
    extern __shared__ float sm[];
    float* As = sm;
    float* Bs = sm + ST * BM * BK;

    const int tid  = threadIdx.x;
    const int warp = tid >> 5, lane = tid & 31;
    const int g    = lane >> 2, qd = lane & 3;
    const int wM   = warp >> 2, wN = warp & 3;
    const int bM   = blockIdx.y * BM, bN = blockIdx.x * BN;
    const uint32_t sw = (uint32_t)(g << 2);

    const uint32_t as_u = smem_u32(As);
    const uint32_t bs_u = smem_u32(Bs);

    float acc[4][4][4];
    #pragma unroll
    for (int i = 0; i < 4; i++)
        #pragma unroll
        for (int j = 0; j < 4; j++)
            #pragma unroll
            for (int e = 0; e < 4; e++) acc[i][j][e] = 0.f;

    const int KT = K / BK;

    auto load_stage = [&](int s, int k0) {
        #pragma unroll
        for (int i = 0; i < 4; i++) {
            int f4 = i * 256 + tid;
            int r  = f4 >> 3;
            int q  = f4 & 7;
            uint32_t col = (uint32_t)(q * 4) ^ (uint32_t)((r & 7) << 2);
            cp16(as_u + (uint32_t)(s * BM * BK + r * BK + col) * 4u,
                 A + (size_t)(bM + r) * K + k0 + q * 4);
            cp16(bs_u + (uint32_t)(s * BN * BK + r * BK + col) * 4u,
                 Bm + (size_t)(bN + r) * K + k0 + q * 4);
        }
        cp_commit();
    };

    #pragma unroll
    for (int s = 0; s < ST - 1; s++) load_stage(s, s * BK);

    for (int t = 0; t < KT; t++) {
        cp_wait<ST - 2>();
        __syncthreads();

        int tn = t + ST - 1;
        if (tn < KT) load_stage(tn % ST, tn * BK);
        else         cp_commit();

        const float* a_st = As + (t % ST) * BM * BK;
        const float* b_st = Bs + (t % ST) * BN * BK;

        #pragma unroll
        for (int kk = 0; kk < 4; kk++) {
            const int k0 = kk * 8 + qd, k1 = k0 + 4;
            uint32_t bf[4][2];
            #pragma unroll
            for (int j = 0; j < 4; j++) {
                int n0 = wN * 32 + j * 8 + g;
                bf[j][0] = __float_as_uint(b_st[n0 * BK + ((uint32_t)k0 ^ sw)]);
                bf[j][1] = __float_as_uint(b_st[n0 * BK + ((uint32_t)k1 ^ sw)]);
            }
            #pragma unroll
            for (int i = 0; i < 4; i++) {
                uint32_t af[4];
                int m0 = wM * 64 + i * 16 + g;
                int m1 = m0 + 8;
                af[0] = __float_as_uint(a_st[m0 * BK + ((uint32_t)k0 ^ sw)]);
                af[1] = __float_as_uint(a_st[m1 * BK + ((uint32_t)k0 ^ sw)]);
                af[2] = __float_as_uint(a_st[m0 * BK + ((uint32_t)k1 ^ sw)]);
                af[3] = __float_as_uint(a_st[m1 * BK + ((uint32_t)k1 ^ sw)]);
                #pragma unroll
                for (int j = 0; j < 4; j++)
                    mma_tf32(acc[i][j], af, bf[j]);
            }
        }
    }

    #pragma unroll
    for (int i = 0; i < 4; i++) {
        #pragma unroll
        for (int j = 0; j < 4; j++) {
            int r0 = bM + wM * 64 + i * 16 + g;
            int c0 = bN + wN * 32 + j * 8 + qd * 2;
            #pragma unroll
            for (int h = 0; h < 2; h++) {
                int r = r0 + h * 8;
                float v0 = acc[i][j][h * 2 + 0];
                float v1 = acc[i][j][h * 2 + 1];
                if (EPI >= 1) { v0 += bias[c0]; v1 += bias[c0 + 1]; }
                if (EPI == 1) {
                    v0 = 0.5f * v0 * (1.f + erff(v0 * 0.70710678118654752f));
                    v1 = 0.5f * v1 * (1.f + erff(v1 * 0.70710678118654752f));
                }
                if (EPI == 2) {
                    const float2 rr = *(const float2*)(res + (size_t)r * Nn + c0);
                    v0 += rr.x; v1 += rr.y;
                }
                if (RND) { v0 = f2tf_f(v0); v1 = f2tf_f(v1); }
                float2 o2; o2.x = v0; o2.y = v1;
                *(float2*)(Cc + (size_t)r * Nn + c0) = o2;
            }
        }
    }
}

// ---------------- Tensor-core flash attention --------------------------------
// K tiles: cp.async double-buffered.  V tiles: register-prefetched one ahead.
__global__ void __launch_bounds__(256)
attn_mma(const float* __restrict__ qkv, float* __restrict__ o)
{
    __shared__ float Ks[2][64][68];   // double-buffered K (cp.async target)
    __shared__ float Vt[64][68];      // V transposed [dim][key]
    __shared__ float Ps[128][68];     // P tile; also Q staging

    const int tid  = threadIdx.x;
    const int warp = tid >> 5, lane = tid & 31;
    const int g    = lane >> 2, qd = lane & 3;
    const int wr   = warp * 16;
    const int b = blockIdx.z, h = blockIdx.y;
    const int q0 = blockIdx.x * 128;
    const int RS = 3 * C_;

    // this thread's 4 (key, dim4) slots for tile loads
    const int j0  = tid >> 4;          // 0..15  (+16 per r)
    const int d40 = (tid & 15) * 4;    // 0..60

    // stage Q into Ps
    for (int i = tid; i < 128 * 16; i += 256) {
        int r = i >> 4, d4 = (i & 15) * 4;
        *(float4*)&Ps[r][d4] =
            *(const float4*)(qkv + (size_t)(b * N_ + q0 + r) * RS + h * DH + d4);
    }
    __syncthreads();

    uint32_t qf[8][4];
    #pragma unroll
    for (int kk = 0; kk < 8; kk++) {
        qf[kk][0] = __float_as_uint(Ps[wr + g    ][kk*8 + qd    ] * 0.125f);
        qf[kk][1] = __float_as_uint(Ps[wr + g + 8][kk*8 + qd    ] * 0.125f);
        qf[kk][2] = __float_as_uint(Ps[wr + g    ][kk*8 + qd + 4] * 0.125f);
        qf[kk][3] = __float_as_uint(Ps[wr + g + 8][kk*8 + qd + 4] * 0.125f);
    }

    float oacc[8][4];
    #pragma unroll
    for (int nb = 0; nb < 8; nb++)
        #pragma unroll
        for (int e = 0; e < 4; e++) oacc[nb][e] = 0.f;
    float m0 = -1e30f, m1 = -1e30f, l0 = 0.f, l1 = 0.f;

    float4 vreg[4];
    auto prefetch = [&](int t) {
        #pragma unroll
        for (int r = 0; r < 4; r++) {
            int j = j0 + r * 16;
            const float* base = qkv + (size_t)(b * N_ + t * 64 + j) * RS + h * DH + d40;
            cp16(smem_u32(&Ks[t & 1][j][d40]), base + C_);
            vreg[r] = *(const float4*)(base + 2 * C_);
        }
        cp_commit();
    };
    prefetch(0);

    for (int t = 0; t < N_ / 64; t++) {
        cp_wait<0>();
        __syncthreads();               // K(t) landed; prior tile reads done
        #pragma unroll
        for (int r = 0; r < 4; r++) {  // store V(t) transposed
            int j = j0 + r * 16;
            Vt[d40 + 0][j] = vreg[r].x; Vt[d40 + 1][j] = vreg[r].y;
            Vt[d40 + 2][j] = vreg[r].z; Vt[d40 + 3][j] = vreg[r].w;
        }
        __syncthreads();
        if (t + 1 < N_ / 64) prefetch(t + 1);   // overlaps with compute below

        const float (*K_)[68] = Ks[t & 1];

        float sacc[8][4];
        #pragma unroll
        for (int nb = 0; nb < 8; nb++)
            #pragma unroll
            for (int e = 0; e < 4; e++) sacc[nb][e] = 0.f;
        #pragma unroll
        for (int kk = 0; kk < 8; kk++) {
            uint32_t bf[8][2];
            #pragma unroll
            for (int nb = 0; nb < 8; nb++) {
                bf[nb][0] = __float_as_uint(K_[nb*8 + g][kk*8 + qd    ]);
                bf[nb][1] = __float_as_uint(K_[nb*8 + g][kk*8 + qd + 4]);
            }
            #pragma unroll
            for (int nb = 0; nb < 8; nb++) mma_tf32(sacc[nb], qf[kk], bf[nb]);
        }

        float mx0 = -1e30f, mx1 = -1e30f;
        #pragma unroll
        for (int nb = 0; nb < 8; nb++) {
            mx0 = fmaxf(mx0, fmaxf(sacc[nb][0], sacc[nb][1]));
            mx1 = fmaxf(mx1, fmaxf(sacc[nb][2], sacc[nb][3]));
        }
        mx0 = fmaxf(mx0, __shfl_xor_sync(0xffffffffu, mx0, 1));
        mx0 = fmaxf(mx0, __shfl_xor_sync(0xffffffffu, mx0, 2));
        mx1 = fmaxf(mx1, __shfl_xor_sync(0xffffffffu, mx1, 1));
        mx1 = fmaxf(mx1, __shfl_xor_sync(0xffffffffu, mx1, 2));

        float mn0 = fmaxf(m0, mx0), mn1 = fmaxf(m1, mx1);
        float c0 = __expf(m0 - mn0), c1 = __expf(m1 - mn1);
        float s0 = 0.f, s1 = 0.f;
        #pragma unroll
        for (int nb = 0; nb < 8; nb++) {
            float p00 = __expf(sacc[nb][0] - mn0);
            float p01 = __expf(sacc[nb][1] - mn0);
            float p10 = __expf(sacc[nb][2] - mn1);
            float p11 = __expf(sacc[nb][3] - mn1);
            s0 += p00 + p01;  s1 += p10 + p11;
            int c = nb * 8 + qd * 2;
            Ps[wr + g    ][c    ] = f2tf_f(p00);
            Ps[wr + g    ][c + 1] = f2tf_f(p01);
            Ps[wr + g + 8][c    ] = f2tf_f(p10);
            Ps[wr + g + 8][c + 1] = f2tf_f(p11);
        }
        s0 += __shfl_xor_sync(0xffffffffu, s0, 1);
        s0 += __shfl_xor_sync(0xffffffffu, s0, 2);
        s1 += __shfl_xor_sync(0xffffffffu, s1, 1);
        s1 += __shfl_xor_sync(0xffffffffu, s1, 2);
        l0 = l0 * c0 + s0;  l1 = l1 * c1 + s1;
        m0 = mn0;  m1 = mn1;
        #pragma unroll
        for (int nb = 0; nb < 8; nb++) {
            oacc[nb][0] *= c0; oacc[nb][1] *= c0;
            oacc[nb][2] *= c1; oacc[nb][3] *= c1;
        }
        __syncwarp();

        #pragma unroll
        for (int kk = 0; kk < 8; kk++) {
            uint32_t af[4];
            af[0] = __float_as_uint(Ps[wr + g    ][kk*8 + qd    ]);
            af[1] = __float_as_uint(Ps[wr + g + 8][kk*8 + qd    ]);
            af[2] = __float_as_uint(Ps[wr + g    ][kk*8 + qd + 4]);
            af[3] = __float_as_uint(Ps[wr + g + 8][kk*8 + qd + 4]);
            uint32_t bf[8][2];
            #pragma unroll
            for (int nb = 0; nb < 8; nb++) {
                bf[nb][0] = __float_as_uint(Vt[nb*8 + g][kk*8 + qd    ]);
                bf[nb][1] = __float_as_uint(Vt[nb*8 + g][kk*8 + qd + 4]);
            }
            #pragma unroll
            for (int nb = 0; nb < 8; nb++) mma_tf32(oacc[nb], af, bf[nb]);
        }
    }

    float i0 = 1.f / l0, i1 = 1.f / l1;
    float* op0 = o + (size_t)(b * N_ + q0 + wr + g    ) * C_ + h * DH;
    float* op1 = o + (size_t)(b * N_ + q0 + wr + g + 8) * C_ + h * DH;
    #pragma unroll
    for (int nb = 0; nb < 8; nb++) {
        int c = nb * 8 + qd * 2;
        float2 a, bb2;
        a.x   = f2tf_f(oacc[nb][0] * i0);  a.y   = f2tf_f(oacc[nb][1] * i0);
        bb2.x = f2tf_f(oacc[nb][2] * i1);  bb2.y = f2tf_f(oacc[nb][3] * i1);
        *(float2*)(op0 + c) = a;
        *(float2*)(op1 + c) = bb2;
    }
}

// ---------------- launch ----------------------------------------------------
extern "C" void kernel_launch(void* const* d_in, const int* in_sizes, int n_in,
                              void* d_out, int out_size)
{
    const float* x      = (const float*)d_in[0];
    const float* qkv_w  = (const float*)d_in[1];
    const float* proj_w = (const float*)d_in[2];
    const float* proj_b = (const float*)d_in[3];
    const float* fc1_w  = (const float*)d_in[4];
    const float* fc1_b  = (const float*)d_in[5];
    const float* fc2_w  = (const float*)d_in[6];
    const float* fc2_b  = (const float*)d_in[7];
    const float* ln1_g  = (const float*)d_in[8];
    const float* ln1_b  = (const float*)d_in[9];
    const float* ln2_g  = (const float*)d_in[10];
    const float* ln2_b  = (const float*)d_in[11];
    const float* lnh_g  = (const float*)d_in[12];
    const float* lnh_b  = (const float*)d_in[13];
    float* out = (float*)d_out;

    float *h, *qkv, *o, *x1, *u, *wq, *wp, *w1, *w2;
    cudaGetSymbolAddress((void**)&h,   g_h);
    cudaGetSymbolAddress((void**)&qkv, g_qkv);
    cudaGetSymbolAddress((void**)&o,   g_o);
    cudaGetSymbolAddress((void**)&x1,  g_x1);
    cudaGetSymbolAddress((void**)&u,   g_u);
    cudaGetSymbolAddress((void**)&wq,  g_wq);
    cudaGetSymbolAddress((void**)&wp,  g_wp);
    cudaGetSymbolAddress((void**)&w1,  g_w1);
    cudaGetSymbolAddress((void**)&w2,  g_w2);

    const int SMEM = 3 * (128 + 128) * 32 * 4;   // 96 KB dynamic
    cudaFuncSetAttribute(gemm_tc<0,true >, cudaFuncAttributeMaxDynamicSharedMemorySize, SMEM);
    cudaFuncSetAttribute(gemm_tc<1,false>, cudaFuncAttributeMaxDynamicSharedMemorySize, SMEM);
    cudaFuncSetAttribute(gemm_tc<2,false>, cudaFuncAttributeMaxDynamicSharedMemorySize, SMEM);

    round_tf32_kernel<<<(3*C_*C_/4 + 255)/256, 256>>>(qkv_w,  wq, 3*C_*C_/4);
    round_tf32_kernel<<<(C_*C_/4   + 255)/256, 256>>>(proj_w, wp, C_*C_/4);
    round_tf32_kernel<<<(DHID*C_/4 + 255)/256, 256>>>(fc1_w,  w1, DHID*C_/4);
    round_tf32_kernel<<<(C_*DHID/4 + 255)/256, 256>>>(fc2_w,  w2, C_*DHID/4);

    ln_kernel<true><<<R_, 256>>>(x, ln1_g, ln1_b, h, C_);
    gemm_tc<0,true><<<dim3(3*C_/128, R_/128), 256, SMEM>>>(h, wq, qkv,
                                                  nullptr, nullptr, R_, 3*C_, C_);
    attn_mma<<<dim3(N_/128, H_, B_), 256>>>(qkv, o);
    gemm_tc<2,false><<<dim3(C_/128, R_/128), 256, SMEM>>>(o, wp, x1,
                                                  proj_b, x, R_, C_, C_);

    ln_kernel<true><<<R_, 256>>>(x1, ln2_g, ln2_b, h, C_);
    gemm_tc<1,false><<<dim3(DHID/128, R_/128), 256, SMEM>>>(h, w1, u,
                                                  fc1_b, nullptr, R_, DHID, C_);
    ln_kernel<true><<<R_, 256>>>(u, lnh_g, lnh_b, u, DHID);
    gemm_tc<2,false><<<dim3(C_/128, R_/128), 256, SMEM>>>(u, w2, out,
                                                  fc2_b, x1, R_, C_, DHID);
}

// round 6
// speedup vs baseline: 6.9863x; 1.7909x over previous
#include <cuda_runtime.h>
#include <cuda_fp16.h>
#include <math.h>
#include <stdint.h>

// Problem constants
#define B_    4
#define N_    1024
#define C_    1024
#define H_    16
#define DH    64
#define DHID  4096
#define R_    (B_*N_)   // 4096 token rows

// ---------------- scratch (device globals: allocation-guard safe) ----------
__device__ __half g_h  [R_*C_];          // LN outputs (half)
__device__ __half g_qkv[R_*3*C_];        // qkv (half)
__device__ __half g_o  [R_*C_];          // attention output (half)
__device__ float  g_x1 [R_*C_];          // residual after attention (fp32)
__device__ __half g_u  [R_*DHID];        // MLP hidden (half), lnh in-place
// half weight copies
__device__ __half g_wq [3*C_*C_];
__device__ __half g_wp [C_*C_];
__device__ __half g_w1 [DHID*C_];
__device__ __half g_w2 [C_*DHID];

// ---------------- PTX helpers ----------------------------------------------
__device__ __forceinline__ uint32_t smem_u32(const void* p){
    uint32_t a;
    asm("{ .reg .u64 t; cvta.to.shared.u64 t, %1; cvt.u32.u64 %0, t; }"
        : "=r"(a) : "l"(p));
    return a;
}
__device__ __forceinline__ void cp16(uint32_t dst, const void* src){
    asm volatile("cp.async.cg.shared.global [%0], [%1], 16;\n" :: "r"(dst), "l"(src));
}
__device__ __forceinline__ void cp_commit(){ asm volatile("cp.async.commit_group;\n"); }
template<int NN>
__device__ __forceinline__ void cp_wait(){ asm volatile("cp.async.wait_group %0;\n" :: "n"(NN)); }
__device__ __forceinline__ void mma_f16(float* d, const uint32_t* a, const uint32_t* b){
    asm volatile(
      "mma.sync.aligned.m16n8k16.row.col.f32.f16.f16.f32 "
      "{%0,%1,%2,%3}, {%4,%5,%6,%7}, {%8,%9}, {%0,%1,%2,%3};\n"
      : "+f"(d[0]), "+f"(d[1]), "+f"(d[2]), "+f"(d[3])
      : "r"(a[0]), "r"(a[1]), "r"(a[2]), "r"(a[3]), "r"(b[0]), "r"(b[1]));
}
__device__ __forceinline__ void store2(float* p, float a, float b){
    float2 t; t.x = a; t.y = b; *(float2*)p = t;
}
__device__ __forceinline__ void store2(__half* p, float a, float b){
    *(__half2*)p = __floats2half2_rn(a, b);
}

// ---------------- fp32 -> fp16 conversion (weights) -------------------------
__global__ void cvt_half_kernel(const float* __restrict__ src,
                                __half* __restrict__ dst, int n4)
{
    int i = blockIdx.x * 256 + threadIdx.x;
    if (i < n4) {
        float4 v = ((const float4*)src)[i];
        __half2 h0 = __floats2half2_rn(v.x, v.y);
        __half2 h1 = __floats2half2_rn(v.z, v.w);
        uint2 r; r.x = *(uint32_t*)&h0; r.y = *(uint32_t*)&h1;
        ((uint2*)dst)[i] = r;
    }
}

// ---------------- LayerNorm (single-pass, register-cached) ------------------
// TI = float or __half input; output half. CC = row width (1024 or 4096).
template<typename TI, int CC>
__global__ void ln_h(const TI* __restrict__ x,
                     const float* __restrict__ g,
                     const float* __restrict__ bb,
                     __half* __restrict__ y)
{
    constexpr int PT = CC / 256;            // elements per thread (4 or 16)
    const int row = blockIdx.x;
    const int tid = threadIdx.x;
    const TI* xr = x + (size_t)row * CC;
    __half*  yr = y + (size_t)row * CC;

    float v[PT];
    float s = 0.f, sq = 0.f;
    #pragma unroll
    for (int i = 0; i < PT / 4; i++) {
        int idx = tid * 4 + i * 1024;
        float4 t;
        if constexpr (sizeof(TI) == 4) {
            t = *(const float4*)((const float*)xr + idx);
        } else {
            uint2 raw = *(const uint2*)((const __half*)xr + idx);
            __half2 h0 = *(__half2*)&raw.x, h1 = *(__half2*)&raw.y;
            float2 f0 = __half22float2(h0), f1 = __half22float2(h1);
            t.x = f0.x; t.y = f0.y; t.z = f1.x; t.w = f1.y;
        }
        v[i*4+0] = t.x; v[i*4+1] = t.y; v[i*4+2] = t.z; v[i*4+3] = t.w;
        s  += t.x + t.y + t.z + t.w;
        sq += t.x*t.x + t.y*t.y + t.z*t.z + t.w*t.w;
    }
    #pragma unroll
    for (int o = 16; o > 0; o >>= 1) {
        s  += __shfl_xor_sync(0xffffffffu, s,  o);
        sq += __shfl_xor_sync(0xffffffffu, sq, o);
    }
    __shared__ float rs[8], rq[8], stats[2];
    int w = tid >> 5, ln = tid & 31;
    if (ln == 0) { rs[w] = s; rq[w] = sq; }
    __syncthreads();
    if (tid == 0) {
        float ts = 0.f, tq = 0.f;
        #pragma unroll
        for (int i = 0; i < 8; i++) { ts += rs[i]; tq += rq[i]; }
        float mu  = ts / (float)CC;
        float var = tq / (float)CC - mu * mu;
        stats[0] = mu;
        stats[1] = rsqrtf(var + 1e-5f);
    }
    __syncthreads();
    float mu = stats[0], r = stats[1];
    #pragma unroll
    for (int i = 0; i < PT / 4; i++) {
        int idx = tid * 4 + i * 1024;
        float4 gg = *(const float4*)(g  + idx);
        float4 be = *(const float4*)(bb + idx);
        float o0 = (v[i*4+0] - mu) * r * gg.x + be.x;
        float o1 = (v[i*4+1] - mu) * r * gg.y + be.y;
        float o2 = (v[i*4+2] - mu) * r * gg.z + be.z;
        float o3 = (v[i*4+3] - mu) * r * gg.w + be.w;
        __half2 h0 = __floats2half2_rn(o0, o1);
        __half2 h1 = __floats2half2_rn(o2, o3);
        uint2 out; out.x = *(uint32_t*)&h0; out.y = *(uint32_t*)&h1;
        *(uint2*)(yr + idx) = out;
    }
}

// ---------------- FP16 tensor-core GEMM (NT): C = A[M,K] @ B[N,K]^T ---------
// A,B half. EPI: 0 plain, 1 +bias+erfGELU, 2 +bias+residual(fp32).
// 128x128x64 tiles, 3-stage cp.async, XOR-swizzled (16B chunk) smem, 2 CTA/SM.
template<int EPI, typename TO>
__global__ void __launch_bounds__(256, 2)
gemm_h(const __half* __restrict__ A, const __half* __restrict__ Bm,
       TO* __restrict__ Cc, const float* __restrict__ bias,
       const float* __restrict__ res, int M, int Nn, int K)
{
    constexpr int BM = 128, BN = 128, BK = 64, ST = 3;
    constexpr int STAGE_H = BM * BK;              // halves per stage (8192)
    extern __shared__ char smc[];
    __half* As = (__half*)smc;                    // ST * STAGE_H
    __half* Bs = As + ST * STAGE_H;

    const int tid  = threadIdx.x;
    const int warp = tid >> 5, lane = tid & 31;
    const int g    = lane >> 2, qd = lane & 3;
    const int wM   = warp >> 2, wN = warp & 3;    // 2 x 4 warp grid
    const int bM   = blockIdx.y * BM, bN = blockIdx.x * BN;

    const uint32_t as_u = smem_u32(As);
    const uint32_t bs_u = smem_u32(Bs);

    float acc[4][4][4];
    #pragma unroll
    for (int i = 0; i < 4; i++)
        #pragma unroll
        for (int j = 0; j < 4; j++)
            #pragma unroll
            for (int e = 0; e < 4; e++) acc[i][j][e] = 0.f;

    const int KT = K / BK;

    auto load_stage = [&](int s, int k0) {
        #pragma unroll
        for (int j = 0; j < 4; j++) {
            int f = tid + j * 256;               // 0..1023
            int r = f >> 3, q = f & 7;           // row, 16B chunk
            uint32_t off = (uint32_t)(r * 128 + ((q ^ (r & 7)) * 16));
            cp16(as_u + (uint32_t)s * 16384u + off,
                 A  + (size_t)(bM + r) * K + k0 + q * 8);
            cp16(bs_u + (uint32_t)s * 16384u + off,
                 Bm + (size_t)(bN + r) * K + k0 + q * 8);
        }
        cp_commit();
    };

    #pragma unroll
    for (int s = 0; s < ST - 1; s++) load_stage(s, s * BK);

    for (int t = 0; t < KT; t++) {
        cp_wait<ST - 2>();
        __syncthreads();

        int tn = t + ST - 1;
        if (tn < KT) load_stage(tn % ST, tn * BK);
        else         cp_commit();

        const __half* a_st = As + (t % ST) * STAGE_H;
        const __half* b_st = Bs + (t % ST) * STAGE_H;

        #pragma unroll
        for (int kk = 0; kk < 4; kk++) {
            const int c0 = 2 * kk, c1 = 2 * kk + 1;
            uint32_t bf[4][2];
            #pragma unroll
            for (int j = 0; j < 4; j++) {
                int n0 = wN * 32 + j * 8 + g;
                int sw = n0 & 7;
                bf[j][0] = *(const uint32_t*)&b_st[n0*64 + ((c0^sw)*8) + 2*qd];
                bf[j][1] = *(const uint32_t*)&b_st[n0*64 + ((c1^sw)*8) + 2*qd];
            }
            #pragma unroll
            for (int i = 0; i < 4; i++) {
                int m0 = wM * 64 + i * 16 + g;
                int m1 = m0 + 8;
                int s0 = m0 & 7, s1 = m1 & 7;
                uint32_t af[4];
                af[0] = *(const uint32_t*)&a_st[m0*64 + ((c0^s0)*8) + 2*qd];
                af[1] = *(const uint32_t*)&a_st[m1*64 + ((c0^s1)*8) + 2*qd];
                af[2] = *(const uint32_t*)&a_st[m0*64 + ((c1^s0)*8) + 2*qd];
                af[3] = *(const uint32_t*)&a_st[m1*64 + ((c1^s1)*8) + 2*qd];
                #pragma unroll
                for (int j = 0; j < 4; j++)
                    mma_f16(acc[i][j], af, bf[j]);
            }
        }
    }

    #pragma unroll
    for (int i = 0; i < 4; i++) {
        #pragma unroll
        for (int j = 0; j < 4; j++) {
            int r0 = bM + wM * 64 + i * 16 + g;
            int c0 = bN + wN * 32 + j * 8 + qd * 2;
            #pragma unroll
            for (int hh = 0; hh < 2; hh++) {
                int r = r0 + hh * 8;
                float v0 = acc[i][j][hh * 2 + 0];
                float v1 = acc[i][j][hh * 2 + 1];
                if (EPI >= 1) { v0 += bias[c0]; v1 += bias[c0 + 1]; }
                if (EPI == 1) {
                    v0 = 0.5f * v0 * (1.f + erff(v0 * 0.70710678118654752f));
                    v1 = 0.5f * v1 * (1.f + erff(v1 * 0.70710678118654752f));
                }
                if (EPI == 2) {
                    const float2 rr = *(const float2*)(res + (size_t)r * Nn + c0);
                    v0 += rr.x; v1 += rr.y;
                }
                store2(Cc + (size_t)r * Nn + c0, v0, v1);
            }
        }
    }
}

// ---------------- FP16 tensor-core flash attention ---------------------------
// grid (8, 16, 4); 256 threads = 8 warps, each owning 16 query rows.
// K tiles (64 keys) cp.async double-buffered; V register-prefetched.
__global__ void __launch_bounds__(256, 2)
attn_mma(const __half* __restrict__ qkv, __half* __restrict__ o)
{
    __shared__ __half Ks[2 * 64 * 64];     // swizzled 128B rows, 16 KB
    __shared__ __half Vt[64 * 72];         // [dim][key], stride 72
    __shared__ __half Ps[128 * 72];        // Q staging / P tile, stride 72

    const int tid  = threadIdx.x;
    const int warp = tid >> 5, lane = tid & 31;
    const int g    = lane >> 2, qd = lane & 3;
    const int wr   = warp * 16;
    const int b = blockIdx.z, h = blockIdx.y;
    const int q0 = blockIdx.x * 128;
    const int RS = 3 * C_;

    const uint32_t ks_u = smem_u32(Ks);

    uint4 vreg[2];
    auto prefetch = [&](int t) {
        #pragma unroll
        for (int e = 0; e < 2; e++) {
            int f = tid + e * 256;
            int r = f >> 3, q = f & 7;
            const __half* base = qkv + (size_t)(b * N_ + t * 64 + r) * RS + h * DH;
            cp16(ks_u + (uint32_t)((t & 1) * 8192 + r * 128 + ((q ^ (r & 7)) * 16)),
                 base + C_ + q * 8);
            vreg[e] = *(const uint4*)(base + 2 * C_ + q * 8);
        }
        cp_commit();
    };
    prefetch(0);

    // stage Q into Ps
    for (int i = tid; i < 128 * 8; i += 256) {
        int r = i >> 3, c = i & 7;
        *(uint4*)&Ps[r * 72 + c * 8] =
            *(const uint4*)(qkv + (size_t)(b * N_ + q0 + r) * RS + h * DH + c * 8);
    }
    __syncthreads();

    // Q fragments (scale 1/8 folded: exact in fp16)
    const __half2 sc = __float2half2_rn(0.125f);
    uint32_t qf[4][4];
    #pragma unroll
    for (int kk = 0; kk < 4; kk++) {
        __half2 t0 = __hmul2(*(__half2*)&Ps[(wr+g  )*72 + kk*16     + 2*qd], sc);
        __half2 t1 = __hmul2(*(__half2*)&Ps[(wr+g+8)*72 + kk*16     + 2*qd], sc);
        __half2 t2 = __hmul2(*(__half2*)&Ps[(wr+g  )*72 + kk*16 + 8 + 2*qd], sc);
        __half2 t3 = __hmul2(*(__half2*)&Ps[(wr+g+8)*72 + kk*16 + 8 + 2*qd], sc);
        qf[kk][0] = *(uint32_t*)&t0; qf[kk][1] = *(uint32_t*)&t1;
        qf[kk][2] = *(uint32_t*)&t2; qf[kk][3] = *(uint32_t*)&t3;
    }

    float oacc[8][4];
    #pragma unroll
    for (int nb = 0; nb < 8; nb++)
        #pragma unroll
        for (int e = 0; e < 4; e++) oacc[nb][e] = 0.f;
    float m0 = -1e30f, m1 = -1e30f, l0 = 0.f, l1 = 0.f;

    for (int t = 0; t < N_ / 64; t++) {
        cp_wait<0>();
        __syncthreads();               // K(t) landed; prior Vt/Ks reads done
        #pragma unroll
        for (int e = 0; e < 2; e++) {  // store V(t) transposed
            int f = tid + e * 256;
            int r = f >> 3, q = f & 7;
            __half hv[8]; *(uint4*)hv = vreg[e];
            #pragma unroll
            for (int x = 0; x < 8; x++)
                Vt[(q * 8 + x) * 72 + r] = hv[x];
        }
        __syncthreads();
        if (t + 1 < N_ / 64) prefetch(t + 1);

        const __half* K_ = Ks + (t & 1) * 4096;

        // S = (Q/8) @ K^T
        float sacc[8][4];
        #pragma unroll
        for (int nb = 0; nb < 8; nb++)
            #pragma unroll
            for (int e = 0; e < 4; e++) sacc[nb][e] = 0.f;
        #pragma unroll
        for (int kk = 0; kk < 4; kk++) {
            const int c0 = 2 * kk, c1 = 2 * kk + 1;
            #pragma unroll
            for (int nb = 0; nb < 8; nb++) {
                int n0 = nb * 8 + g, sw = n0 & 7;
                uint32_t bf[2];
                bf[0] = *(const uint32_t*)&K_[n0*64 + ((c0^sw)*8) + 2*qd];
                bf[1] = *(const uint32_t*)&K_[n0*64 + ((c1^sw)*8) + 2*qd];
                mma_f16(sacc[nb], qf[kk], bf);
            }
        }

        // online softmax (rows g / g+8; stats across quad lanes)
        float mx0 = -1e30f, mx1 = -1e30f;
        #pragma unroll
        for (int nb = 0; nb < 8; nb++) {
            mx0 = fmaxf(mx0, fmaxf(sacc[nb][0], sacc[nb][1]));
            mx1 = fmaxf(mx1, fmaxf(sacc[nb][2], sacc[nb][3]));
        }
        mx0 = fmaxf(mx0, __shfl_xor_sync(0xffffffffu, mx0, 1));
        mx0 = fmaxf(mx0, __shfl_xor_sync(0xffffffffu, mx0, 2));
        mx1 = fmaxf(mx1, __shfl_xor_sync(0xffffffffu, mx1, 1));
        mx1 = fmaxf(mx1, __shfl_xor_sync(0xffffffffu, mx1, 2));

        float mn0 = fmaxf(m0, mx0), mn1 = fmaxf(m1, mx1);
        float cc0 = __expf(m0 - mn0), cc1 = __expf(m1 - mn1);
        float s0 = 0.f, s1 = 0.f;
        #pragma unroll
        for (int nb = 0; nb < 8; nb++) {
            float p00 = __expf(sacc[nb][0] - mn0);
            float p01 = __expf(sacc[nb][1] - mn0);
            float p10 = __expf(sacc[nb][2] - mn1);
            float p11 = __expf(sacc[nb][3] - mn1);
            s0 += p00 + p01;  s1 += p10 + p11;
            *(__half2*)&Ps[(wr+g  )*72 + nb*8 + 2*qd] = __floats2half2_rn(p00, p01);
            *(__half2*)&Ps[(wr+g+8)*72 + nb*8 + 2*qd] = __floats2half2_rn(p10, p11);
        }
        s0 += __shfl_xor_sync(0xffffffffu, s0, 1);
        s0 += __shfl_xor_sync(0xffffffffu, s0, 2);
        s1 += __shfl_xor_sync(0xffffffffu, s1, 1);
        s1 += __shfl_xor_sync(0xffffffffu, s1, 2);
        l0 = l0 * cc0 + s0;  l1 = l1 * cc1 + s1;
        m0 = mn0;  m1 = mn1;
        #pragma unroll
        for (int nb = 0; nb < 8; nb++) {
            oacc[nb][0] *= cc0; oacc[nb][1] *= cc0;
            oacc[nb][2] *= cc1; oacc[nb][3] *= cc1;
        }
        __syncwarp();

        // O += P @ V
        #pragma unroll
        for (int jc = 0; jc < 4; jc++) {
            uint32_t af[4];
            af[0] = *(const uint32_t*)&Ps[(wr+g  )*72 + jc*16     + 2*qd];
            af[1] = *(const uint32_t*)&Ps[(wr+g+8)*72 + jc*16     + 2*qd];
            af[2] = *(const uint32_t*)&Ps[(wr+g  )*72 + jc*16 + 8 + 2*qd];
            af[3] = *(const uint32_t*)&Ps[(wr+g+8)*72 + jc*16 + 8 + 2*qd];
            #pragma unroll
            for (int nb = 0; nb < 8; nb++) {
                int d0 = nb * 8 + g;
                uint32_t bf[2];
                bf[0] = *(const uint32_t*)&Vt[d0*72 + jc*16     + 2*qd];
                bf[1] = *(const uint32_t*)&Vt[d0*72 + jc*16 + 8 + 2*qd];
                mma_f16(oacc[nb], af, bf);
            }
        }
    }

    float i0 = 1.f / l0, i1 = 1.f / l1;
    __half* op0 = o + (size_t)(b * N_ + q0 + wr + g    ) * C_ + h * DH;
    __half* op1 = o + (size_t)(b * N_ + q0 + wr + g + 8) * C_ + h * DH;
    #pragma unroll
    for (int nb = 0; nb < 8; nb++) {
        int c = nb * 8 + qd * 2;
        *(__half2*)(op0 + c) = __floats2half2_rn(oacc[nb][0] * i0, oacc[nb][1] * i0);
        *(__half2*)(op1 + c) = __floats2half2_rn(oacc[nb][2] * i1, oacc[nb][3] * i1);
    }
}

// ---------------- launch ----------------------------------------------------
extern "C" void kernel_launch(void* const* d_in, const int* in_sizes, int n_in,
                              void* d_out, int out_size)
{
    const float* x      = (const float*)d_in[0];
    const float* qkv_w  = (const float*)d_in[1];
    const float* proj_w = (const float*)d_in[2];
    const float* proj_b = (const float*)d_in[3];
    const float* fc1_w  = (const float*)d_in[4];
    const float* fc1_b  = (const float*)d_in[5];
    const float* fc2_w  = (const float*)d_in[6];
    const float* fc2_b  = (const float*)d_in[7];
    const float* ln1_g  = (const float*)d_in[8];
    const float* ln1_b  = (const float*)d_in[9];
    const float* ln2_g  = (const float*)d_in[10];
    const float* ln2_b  = (const float*)d_in[11];
    const float* lnh_g  = (const float*)d_in[12];
    const float* lnh_b  = (const float*)d_in[13];
    float* out = (float*)d_out;

    __half *h, *qkv, *o, *u, *wq, *wp, *w1, *w2;
    float *x1;
    cudaGetSymbolAddress((void**)&h,   g_h);
    cudaGetSymbolAddress((void**)&qkv, g_qkv);
    cudaGetSymbolAddress((void**)&o,   g_o);
    cudaGetSymbolAddress((void**)&x1,  g_x1);
    cudaGetSymbolAddress((void**)&u,   g_u);
    cudaGetSymbolAddress((void**)&wq,  g_wq);
    cudaGetSymbolAddress((void**)&wp,  g_wp);
    cudaGetSymbolAddress((void**)&w1,  g_w1);
    cudaGetSymbolAddress((void**)&w2,  g_w2);

    const int SMEM = 3 * 128 * 64 * 2 * 2;   // 96 KB dynamic
    cudaFuncSetAttribute(gemm_h<0,__half>, cudaFuncAttributeMaxDynamicSharedMemorySize, SMEM);
    cudaFuncSetAttribute(gemm_h<1,__half>, cudaFuncAttributeMaxDynamicSharedMemorySize, SMEM);
    cudaFuncSetAttribute(gemm_h<2,float >, cudaFuncAttributeMaxDynamicSharedMemorySize, SMEM);

    // weight conversion fp32 -> fp16
    cvt_half_kernel<<<(3*C_*C_/4 + 255)/256, 256>>>(qkv_w,  wq, 3*C_*C_/4);
    cvt_half_kernel<<<(C_*C_/4   + 255)/256, 256>>>(proj_w, wp, C_*C_/4);
    cvt_half_kernel<<<(DHID*C_/4 + 255)/256, 256>>>(fc1_w,  w1, DHID*C_/4);
    cvt_half_kernel<<<(C_*DHID/4 + 255)/256, 256>>>(fc2_w,  w2, C_*DHID/4);

    // --- attention sublayer ---
    ln_h<float, C_><<<R_, 256>>>(x, ln1_g, ln1_b, h);
    gemm_h<0,__half><<<dim3(3*C_/128, R_/128), 256, SMEM>>>(h, wq, qkv,
                                                   nullptr, nullptr, R_, 3*C_, C_);
    attn_mma<<<dim3(N_/128, H_, B_), 256>>>(qkv, o);
    gemm_h<2,float><<<dim3(C_/128, R_/128), 256, SMEM>>>(o, wp, x1,
                                                   proj_b, x, R_, C_, C_);

    // --- MLP sublayer ---
    ln_h<float, C_><<<R_, 256>>>(x1, ln2_g, ln2_b, h);
    gemm_h<1,__half><<<dim3(DHID/128, R_/128), 256, SMEM>>>(h, w1, u,
                                                   fc1_b, nullptr, R_, DHID, C_);
    ln_h<__half, DHID><<<R_, 256>>>(u, lnh_g, lnh_b, u);
    gemm_h<2,float><<<dim3(C_/128, R_/128), 256, SMEM>>>(u, w2, out,
                                                   fc2_b, x1, R_, C_, DHID);
}

// round 7
// speedup vs baseline: 8.0319x; 1.1497x over previous
#include <cuda_runtime.h>
#include <cuda_fp16.h>
#include <math.h>
#include <stdint.h>

// Problem constants
#define B_    4
#define N_    1024
#define C_    1024
#define H_    16
#define DH    64
#define DHID  4096
#define R_    (B_*N_)   // 4096 token rows

// ---------------- scratch (device globals: allocation-guard safe) ----------
__device__ __half g_h  [R_*C_];          // LN outputs (half)
__device__ __half g_qkv[R_*3*C_];        // qkv (half)
__device__ __half g_o  [R_*C_];          // attention output (half)
__device__ float  g_x1 [R_*C_];          // residual after attention (fp32)
__device__ __half g_u  [R_*DHID];        // MLP hidden (half), lnh in-place
// half weight copies
__device__ __half g_wq [3*C_*C_];
__device__ __half g_wp [C_*C_];
__device__ __half g_w1 [DHID*C_];
__device__ __half g_w2 [C_*DHID];

// ---------------- PTX helpers ----------------------------------------------
__device__ __forceinline__ uint32_t smem_u32(const void* p){
    uint32_t a;
    asm("{ .reg .u64 t; cvta.to.shared.u64 t, %1; cvt.u32.u64 %0, t; }"
        : "=r"(a) : "l"(p));
    return a;
}
__device__ __forceinline__ void cp16(uint32_t dst, const void* src){
    asm volatile("cp.async.cg.shared.global [%0], [%1], 16;\n" :: "r"(dst), "l"(src));
}
__device__ __forceinline__ void cp_commit(){ asm volatile("cp.async.commit_group;\n"); }
template<int NN>
__device__ __forceinline__ void cp_wait(){ asm volatile("cp.async.wait_group %0;\n" :: "n"(NN)); }
__device__ __forceinline__ void mma_f16(float* d, const uint32_t* a, const uint32_t* b){
    asm volatile(
      "mma.sync.aligned.m16n8k16.row.col.f32.f16.f16.f32 "
      "{%0,%1,%2,%3}, {%4,%5,%6,%7}, {%8,%9}, {%0,%1,%2,%3};\n"
      : "+f"(d[0]), "+f"(d[1]), "+f"(d[2]), "+f"(d[3])
      : "r"(a[0]), "r"(a[1]), "r"(a[2]), "r"(a[3]), "r"(b[0]), "r"(b[1]));
}
__device__ __forceinline__ void ldsm4(uint32_t* r, uint32_t a){
    asm volatile("ldmatrix.sync.aligned.m8n8.x4.shared.b16 {%0,%1,%2,%3}, [%4];"
      : "=r"(r[0]), "=r"(r[1]), "=r"(r[2]), "=r"(r[3]) : "r"(a));
}
__device__ __forceinline__ void ldsm4t(uint32_t* r, uint32_t a){
    asm volatile("ldmatrix.sync.aligned.m8n8.x4.trans.shared.b16 {%0,%1,%2,%3}, [%4];"
      : "=r"(r[0]), "=r"(r[1]), "=r"(r[2]), "=r"(r[3]) : "r"(a));
}
__device__ __forceinline__ void store2(float* p, float a, float b){
    float2 t; t.x = a; t.y = b; *(float2*)p = t;
}
__device__ __forceinline__ void store2(__half* p, float a, float b){
    *(__half2*)p = __floats2half2_rn(a, b);
}

// ---------------- fp32 -> fp16 conversion (weights) -------------------------
__global__ void cvt_half_kernel(const float* __restrict__ src,
                                __half* __restrict__ dst, int n4)
{
    int i = blockIdx.x * 256 + threadIdx.x;
    if (i < n4) {
        float4 v = ((const float4*)src)[i];
        __half2 h0 = __floats2half2_rn(v.x, v.y);
        __half2 h1 = __floats2half2_rn(v.z, v.w);
        uint2 r; r.x = *(uint32_t*)&h0; r.y = *(uint32_t*)&h1;
        ((uint2*)dst)[i] = r;
    }
}

// ---------------- LayerNorm (single-pass, register-cached) ------------------
template<typename TI, int CC>
__global__ void ln_h(const TI* __restrict__ x,
                     const float* __restrict__ g,
                     const float* __restrict__ bb,
                     __half* __restrict__ y)
{
    constexpr int PT = CC / 256;
    const int row = blockIdx.x;
    const int tid = threadIdx.x;
    const TI* xr = x + (size_t)row * CC;
    __half*  yr = y + (size_t)row * CC;

    float v[PT];
    float s = 0.f, sq = 0.f;
    #pragma unroll
    for (int i = 0; i < PT / 4; i++) {
        int idx = tid * 4 + i * 1024;
        float4 t;
        if constexpr (sizeof(TI) == 4) {
            t = *(const float4*)((const float*)xr + idx);
        } else {
            uint2 raw = *(const uint2*)((const __half*)xr + idx);
            __half2 h0 = *(__half2*)&raw.x, h1 = *(__half2*)&raw.y;
            float2 f0 = __half22float2(h0), f1 = __half22float2(h1);
            t.x = f0.x; t.y = f0.y; t.z = f1.x; t.w = f1.y;
        }
        v[i*4+0] = t.x; v[i*4+1] = t.y; v[i*4+2] = t.z; v[i*4+3] = t.w;
        s  += t.x + t.y + t.z + t.w;
        sq += t.x*t.x + t.y*t.y + t.z*t.z + t.w*t.w;
    }
    #pragma unroll
    for (int o = 16; o > 0; o >>= 1) {
        s  += __shfl_xor_sync(0xffffffffu, s,  o);
        sq += __shfl_xor_sync(0xffffffffu, sq, o);
    }
    __shared__ float rs[8], rq[8], stats[2];
    int w = tid >> 5, ln = tid & 31;
    if (ln == 0) { rs[w] = s; rq[w] = sq; }
    __syncthreads();
    if (tid == 0) {
        float ts = 0.f, tq = 0.f;
        #pragma unroll
        for (int i = 0; i < 8; i++) { ts += rs[i]; tq += rq[i]; }
        float mu  = ts / (float)CC;
        float var = tq / (float)CC - mu * mu;
        stats[0] = mu;
        stats[1] = rsqrtf(var + 1e-5f);
    }
    __syncthreads();
    float mu = stats[0], r = stats[1];
    #pragma unroll
    for (int i = 0; i < PT / 4; i++) {
        int idx = tid * 4 + i * 1024;
        float4 gg = *(const float4*)(g  + idx);
        float4 be = *(const float4*)(bb + idx);
        float o0 = (v[i*4+0] - mu) * r * gg.x + be.x;
        float o1 = (v[i*4+1] - mu) * r * gg.y + be.y;
        float o2 = (v[i*4+2] - mu) * r * gg.z + be.z;
        float o3 = (v[i*4+3] - mu) * r * gg.w + be.w;
        __half2 h0 = __floats2half2_rn(o0, o1);
        __half2 h1 = __floats2half2_rn(o2, o3);
        uint2 out; out.x = *(uint32_t*)&h0; out.y = *(uint32_t*)&h1;
        *(uint2*)(yr + idx) = out;
    }
}

// ---------------- FP16 tensor-core GEMM (NT): C = A[M,K] @ B[N,K]^T ---------
// 128x128x64 tiles, 3-stage cp.async, XOR-swizzled smem, ldmatrix fragments.
template<int EPI, typename TO>
__global__ void __launch_bounds__(256, 2)
gemm_h(const __half* __restrict__ A, const __half* __restrict__ Bm,
       TO* __restrict__ Cc, const float* __restrict__ bias,
       const float* __restrict__ res, int M, int Nn, int K)
{
    constexpr int BM = 128, BN = 128, BK = 64, ST = 3;
    constexpr int STAGE_H = BM * BK;              // halves per stage (8192)
    extern __shared__ char smc[];
    __half* As = (__half*)smc;
    __half* Bs = As + ST * STAGE_H;

    const int tid  = threadIdx.x;
    const int warp = tid >> 5, lane = tid & 31;
    const int g    = lane >> 2, qd = lane & 3;
    const int wM   = warp >> 2, wN = warp & 3;
    const int bM   = blockIdx.y * BM, bN = blockIdx.x * BN;

    const uint32_t as_u = smem_u32(As);
    const uint32_t bs_u = smem_u32(Bs);

    // per-lane ldmatrix row/chunk assignments
    const int l7 = lane & 7;
    int aRow[4], bRow[2];
    #pragma unroll
    for (int i = 0; i < 4; i++)
        aRow[i] = wM * 64 + i * 16 + l7 + ((lane >> 3) & 1) * 8;
    const int cA = (lane >> 4) & 1;
    #pragma unroll
    for (int jj = 0; jj < 2; jj++)
        bRow[jj] = wN * 32 + jj * 16 + l7 + ((lane >> 4) & 1) * 8;
    const int cB = (lane >> 3) & 1;

    float acc[4][4][4];
    #pragma unroll
    for (int i = 0; i < 4; i++)
        #pragma unroll
        for (int j = 0; j < 4; j++)
            #pragma unroll
            for (int e = 0; e < 4; e++) acc[i][j][e] = 0.f;

    const int KT = K / BK;

    auto load_stage = [&](int s, int k0) {
        #pragma unroll
        for (int j = 0; j < 4; j++) {
            int f = tid + j * 256;
            int r = f >> 3, q = f & 7;
            uint32_t off = (uint32_t)(r * 128 + ((q ^ (r & 7)) * 16));
            cp16(as_u + (uint32_t)s * 16384u + off,
                 A  + (size_t)(bM + r) * K + k0 + q * 8);
            cp16(bs_u + (uint32_t)s * 16384u + off,
                 Bm + (size_t)(bN + r) * K + k0 + q * 8);
        }
        cp_commit();
    };

    #pragma unroll
    for (int s = 0; s < ST - 1; s++) load_stage(s, s * BK);

    for (int t = 0; t < KT; t++) {
        cp_wait<ST - 2>();
        __syncthreads();

        int tn = t + ST - 1;
        if (tn < KT) load_stage(tn % ST, tn * BK);
        else         cp_commit();

        const uint32_t a_st = as_u + (uint32_t)(t % ST) * 16384u;
        const uint32_t b_st = bs_u + (uint32_t)(t % ST) * 16384u;

        #pragma unroll
        for (int kk = 0; kk < 4; kk++) {
            const int chA = 2 * kk + cA;
            const int chB = 2 * kk + cB;
            uint32_t bf[2][4];
            #pragma unroll
            for (int jj = 0; jj < 2; jj++)
                ldsm4(bf[jj], b_st + (uint32_t)(bRow[jj] * 128
                                 + ((chB ^ (bRow[jj] & 7)) * 16)));
            #pragma unroll
            for (int i = 0; i < 4; i++) {
                uint32_t af[4];
                ldsm4(af, a_st + (uint32_t)(aRow[i] * 128
                               + ((chA ^ (aRow[i] & 7)) * 16)));
                #pragma unroll
                for (int j = 0; j < 4; j++)
                    mma_f16(acc[i][j], af, &bf[j >> 1][(j & 1) * 2]);
            }
        }
    }

    #pragma unroll
    for (int i = 0; i < 4; i++) {
        #pragma unroll
        for (int j = 0; j < 4; j++) {
            int r0 = bM + wM * 64 + i * 16 + g;
            int c0 = bN + wN * 32 + j * 8 + qd * 2;
            #pragma unroll
            for (int hh = 0; hh < 2; hh++) {
                int r = r0 + hh * 8;
                float v0 = acc[i][j][hh * 2 + 0];
                float v1 = acc[i][j][hh * 2 + 1];
                if (EPI >= 1) { v0 += bias[c0]; v1 += bias[c0 + 1]; }
                if (EPI == 1) {
                    v0 = 0.5f * v0 * (1.f + erff(v0 * 0.70710678118654752f));
                    v1 = 0.5f * v1 * (1.f + erff(v1 * 0.70710678118654752f));
                }
                if (EPI == 2) {
                    const float2 rr = *(const float2*)(res + (size_t)r * Nn + c0);
                    v0 += rr.x; v1 += rr.y;
                }
                store2(Cc + (size_t)r * Nn + c0, v0, v1);
            }
        }
    }
}

// ---------------- FP16 tensor-core flash attention ---------------------------
// K and V cp.async double-buffered into swizzled smem; V fragments via
// ldmatrix.trans (no explicit transpose pass). grid (8,16,4), 256 thr.
__global__ void __launch_bounds__(256, 2)
attn_mma(const __half* __restrict__ qkv, __half* __restrict__ o)
{
    // dynamic smem: Ks 2x8KB | Vs 2x8KB | Ps 128x72 halves (18KB)
    extern __shared__ char smc[];
    const uint32_t sb   = smem_u32(smc);
    const uint32_t ks_u = sb;
    const uint32_t vs_u = sb + 16384;
    const uint32_t ps_u = sb + 32768;
    __half* Ps = (__half*)(smc + 32768);

    const int tid  = threadIdx.x;
    const int warp = tid >> 5, lane = tid & 31;
    const int g    = lane >> 2, qd = lane & 3;
    const int l7   = lane & 7;
    const int wr   = warp * 16;
    const int b = blockIdx.z, h = blockIdx.y;
    const int q0 = blockIdx.x * 128;
    const int RS = 3 * C_;
    const int NT = N_ / 64;

    auto prefetch = [&](int t) {
        #pragma unroll
        for (int e = 0; e < 2; e++) {
            int f = tid + e * 256;
            int r = f >> 3, q = f & 7;
            uint32_t off = (uint32_t)((t & 1) * 8192 + r * 128 + ((q ^ (r & 7)) * 16));
            const __half* base = qkv + (size_t)(b * N_ + t * 64 + r) * RS + h * DH + q * 8;
            cp16(ks_u + off, base + C_);
            cp16(vs_u + off, base + 2 * C_);
        }
        cp_commit();
    };
    prefetch(0);

    // stage Q into Ps (row stride 72 halves)
    for (int i = tid; i < 128 * 8; i += 256) {
        int r = i >> 3, c = i & 7;
        *(uint4*)&Ps[r * 72 + c * 8] =
            *(const uint4*)(qkv + (size_t)(b * N_ + q0 + r) * RS + h * DH + c * 8);
    }
    __syncthreads();

    // Q fragments via ldmatrix, then fold scale 1/8 (exact in fp16)
    const __half2 sc = __float2half2_rn(0.125f);
    uint32_t qf[4][4];
    {
        const int qrow = wr + l7 + ((lane >> 3) & 1) * 8;
        const int qch  = (lane >> 4) & 1;
        #pragma unroll
        for (int kk = 0; kk < 4; kk++) {
            ldsm4(qf[kk], ps_u + (uint32_t)(qrow * 144 + (2 * kk + qch) * 16));
            #pragma unroll
            for (int e = 0; e < 4; e++) {
                __half2 t = __hmul2(*(__half2*)&qf[kk][e], sc);
                qf[kk][e] = *(uint32_t*)&t;
            }
        }
    }

    float oacc[8][4];
    #pragma unroll
    for (int nb = 0; nb < 8; nb++)
        #pragma unroll
        for (int e = 0; e < 4; e++) oacc[nb][e] = 0.f;
    float m0 = -1e30f, m1 = -1e30f, l0 = 0.f, l1 = 0.f;

    // ldmatrix lane assignments
    const int kRow = l7 + ((lane >> 4) & 1) * 8;   // + p*16 (K, non-trans)
    const int kCh  = (lane >> 3) & 1;              // + 2*kk
    const int vRow = l7 + ((lane >> 3) & 1) * 8;   // + jc*16 (V, trans)
    const int vCh  = (lane >> 4) & 1;              // + 2*p
    const int pRow = wr + l7 + ((lane >> 3) & 1) * 8;
    const int pCh  = (lane >> 4) & 1;              // + 2*jc

    for (int t = 0; t < NT; t++) {
        cp_wait<0>();
        __syncthreads();                    // K/V(t) visible; stage t-1 reads done
        if (t + 1 < NT) prefetch(t + 1);

        const uint32_t K_ = ks_u + (uint32_t)((t & 1) * 8192);
        const uint32_t V_ = vs_u + (uint32_t)((t & 1) * 8192);

        // S = (Q/8) @ K^T
        float sacc[8][4];
        #pragma unroll
        for (int nb = 0; nb < 8; nb++)
            #pragma unroll
            for (int e = 0; e < 4; e++) sacc[nb][e] = 0.f;
        #pragma unroll
        for (int kk = 0; kk < 4; kk++) {
            uint32_t bf[4][4];
            #pragma unroll
            for (int p = 0; p < 4; p++) {
                int row = p * 16 + kRow;
                ldsm4(bf[p], K_ + (uint32_t)(row * 128
                            + (((2 * kk + kCh) ^ (row & 7)) * 16)));
            }
            #pragma unroll
            for (int nb = 0; nb < 8; nb++)
                mma_f16(sacc[nb], qf[kk], &bf[nb >> 1][(nb & 1) * 2]);
        }

        // online softmax
        float mx0 = -1e30f, mx1 = -1e30f;
        #pragma unroll
        for (int nb = 0; nb < 8; nb++) {
            mx0 = fmaxf(mx0, fmaxf(sacc[nb][0], sacc[nb][1]));
            mx1 = fmaxf(mx1, fmaxf(sacc[nb][2], sacc[nb][3]));
        }
        mx0 = fmaxf(mx0, __shfl_xor_sync(0xffffffffu, mx0, 1));
        mx0 = fmaxf(mx0, __shfl_xor_sync(0xffffffffu, mx0, 2));
        mx1 = fmaxf(mx1, __shfl_xor_sync(0xffffffffu, mx1, 1));
        mx1 = fmaxf(mx1, __shfl_xor_sync(0xffffffffu, mx1, 2));

        float mn0 = fmaxf(m0, mx0), mn1 = fmaxf(m1, mx1);
        float cc0 = __expf(m0 - mn0), cc1 = __expf(m1 - mn1);
        float s0 = 0.f, s1 = 0.f;
        #pragma unroll
        for (int nb = 0; nb < 8; nb++) {
            float p00 = __expf(sacc[nb][0] - mn0);
            float p01 = __expf(sacc[nb][1] - mn0);
            float p10 = __expf(sacc[nb][2] - mn1);
            float p11 = __expf(sacc[nb][3] - mn1);
            s0 += p00 + p01;  s1 += p10 + p11;
            *(__half2*)&Ps[(wr+g  )*72 + nb*8 + 2*qd] = __floats2half2_rn(p00, p01);
            *(__half2*)&Ps[(wr+g+8)*72 + nb*8 + 2*qd] = __floats2half2_rn(p10, p11);
        }
        s0 += __shfl_xor_sync(0xffffffffu, s0, 1);
        s0 += __shfl_xor_sync(0xffffffffu, s0, 2);
        s1 += __shfl_xor_sync(0xffffffffu, s1, 1);
        s1 += __shfl_xor_sync(0xffffffffu, s1, 2);
        l0 = l0 * cc0 + s0;  l1 = l1 * cc1 + s1;
        m0 = mn0;  m1 = mn1;
        #pragma unroll
        for (int nb = 0; nb < 8; nb++) {
            oacc[nb][0] *= cc0; oacc[nb][1] *= cc0;
            oacc[nb][2] *= cc1; oacc[nb][3] *= cc1;
        }
        __syncwarp();

        // O += P @ V   (V fragments via ldmatrix.trans on row-major V tile)
        #pragma unroll
        for (int jc = 0; jc < 4; jc++) {
            uint32_t af[4];
            ldsm4(af, ps_u + (uint32_t)(pRow * 144 + (2 * jc + pCh) * 16));
            uint32_t bf[4][4];
            #pragma unroll
            for (int p = 0; p < 4; p++) {
                int row = jc * 16 + vRow;
                ldsm4t(bf[p], V_ + (uint32_t)(row * 128
                             + (((2 * p + vCh) ^ (row & 7)) * 16)));
            }
            #pragma unroll
            for (int nb = 0; nb < 8; nb++)
                mma_f16(oacc[nb], af, &bf[nb >> 1][(nb & 1) * 2]);
        }
    }

    float i0 = 1.f / l0, i1 = 1.f / l1;
    __half* op0 = o + (size_t)(b * N_ + q0 + wr + g    ) * C_ + h * DH;
    __half* op1 = o + (size_t)(b * N_ + q0 + wr + g + 8) * C_ + h * DH;
    #pragma unroll
    for (int nb = 0; nb < 8; nb++) {
        int c = nb * 8 + qd * 2;
        *(__half2*)(op0 + c) = __floats2half2_rn(oacc[nb][0] * i0, oacc[nb][1] * i0);
        *(__half2*)(op1 + c) = __floats2half2_rn(oacc[nb][2] * i1, oacc[nb][3] * i1);
    }
}

// ---------------- launch ----------------------------------------------------
extern "C" void kernel_launch(void* const* d_in, const int* in_sizes, int n_in,
                              void* d_out, int out_size)
{
    const float* x      = (const float*)d_in[0];
    const float* qkv_w  = (const float*)d_in[1];
    const float* proj_w = (const float*)d_in[2];
    const float* proj_b = (const float*)d_in[3];
    const float* fc1_w  = (const float*)d_in[4];
    const float* fc1_b  = (const float*)d_in[5];
    const float* fc2_w  = (const float*)d_in[6];
    const float* fc2_b  = (const float*)d_in[7];
    const float* ln1_g  = (const float*)d_in[8];
    const float* ln1_b  = (const float*)d_in[9];
    const float* ln2_g  = (const float*)d_in[10];
    const float* ln2_b  = (const float*)d_in[11];
    const float* lnh_g  = (const float*)d_in[12];
    const float* lnh_b  = (const float*)d_in[13];
    float* out = (float*)d_out;

    __half *h, *qkv, *o, *u, *wq, *wp, *w1, *w2;
    float *x1;
    cudaGetSymbolAddress((void**)&h,   g_h);
    cudaGetSymbolAddress((void**)&qkv, g_qkv);
    cudaGetSymbolAddress((void**)&o,   g_o);
    cudaGetSymbolAddress((void**)&x1,  g_x1);
    cudaGetSymbolAddress((void**)&u,   g_u);
    cudaGetSymbolAddress((void**)&wq,  g_wq);
    cudaGetSymbolAddress((void**)&wp,  g_wp);
    cudaGetSymbolAddress((void**)&w1,  g_w1);
    cudaGetSymbolAddress((void**)&w2,  g_w2);

    const int SMEM  = 3 * 128 * 64 * 2 * 2;          // 96 KB (GEMM)
    const int ASMEM = 16384 + 16384 + 128 * 72 * 2;  // 50.5 KB (attention)
    cudaFuncSetAttribute(gemm_h<0,__half>, cudaFuncAttributeMaxDynamicSharedMemorySize, SMEM);
    cudaFuncSetAttribute(gemm_h<1,__half>, cudaFuncAttributeMaxDynamicSharedMemorySize, SMEM);
    cudaFuncSetAttribute(gemm_h<2,float >, cudaFuncAttributeMaxDynamicSharedMemorySize, SMEM);
    cudaFuncSetAttribute(attn_mma,         cudaFuncAttributeMaxDynamicSharedMemorySize, ASMEM);

    // weight conversion fp32 -> fp16
    cvt_half_kernel<<<(3*C_*C_/4 + 255)/256, 256>>>(qkv_w,  wq, 3*C_*C_/4);
    cvt_half_kernel<<<(C_*C_/4   + 255)/256, 256>>>(proj_w, wp, C_*C_/4);
    cvt_half_kernel<<<(DHID*C_/4 + 255)/256, 256>>>(fc1_w,  w1, DHID*C_/4);
    cvt_half_kernel<<<(C_*DHID/4 + 255)/256, 256>>>(fc2_w,  w2, C_*DHID/4);

    // --- attention sublayer ---
    ln_h<float, C_><<<R_, 256>>>(x, ln1_g, ln1_b, h);
    gemm_h<0,__half><<<dim3(3*C_/128, R_/128), 256, SMEM>>>(h, wq, qkv,
                                                   nullptr, nullptr, R_, 3*C_, C_);
    attn_mma<<<dim3(N_/128, H_, B_), 256, ASMEM>>>(qkv, o);
    gemm_h<2,float><<<dim3(C_/128, R_/128), 256, SMEM>>>(o, wp, x1,
                                                   proj_b, x, R_, C_, C_);

    // --- MLP sublayer ---
    ln_h<float, C_><<<R_, 256>>>(x1, ln2_g, ln2_b, h);
    gemm_h<1,__half><<<dim3(DHID/128, R_/128), 256, SMEM>>>(h, w1, u,
                                                   fc1_b, nullptr, R_, DHID, C_);
    ln_h<__half, DHID><<<R_, 256>>>(u, lnh_g, lnh_b, u);
    gemm_h<2,float><<<dim3(C_/128, R_/128), 256, SMEM>>>(u, w2, out,
                                                   fc2_b, x1, R_, C_, DHID);
}